// round 9
// baseline (speedup 1.0000x reference)
#include <cuda_runtime.h>
#include <cuda_bf16.h>
#include <cstdint>

#define B_   8
#define L_   1024
#define D_   512
#define H_   8
#define DK_  64
#define KW_  7
#define PAD_ 3
#define NCAT 448    /* KW*DK */
#define KSP_ROWS 1030

// ---------------- scratch (device globals; no runtime allocation) ----------
__device__ float g_qs[B_*L_*D_];
__device__ float g_ks[B_*L_*D_];
__device__ float g_vs[B_*L_*D_];
__device__ float g_bcat[H_*NCAT];
// bf16 hi/lo operands
__device__ __align__(16) __nv_bfloat16 g_qcat_hi[(size_t)B_*H_*L_*NCAT];
__device__ __align__(16) __nv_bfloat16 g_qcat_lo[(size_t)B_*H_*L_*NCAT];
// padded k_s bf16 split: [z][1030][64], rows 0-2 & 1027-1029 zero
__device__ __align__(16) __nv_bfloat16 g_ksp_hi[(size_t)B_*H_*KSP_ROWS*DK_];
__device__ __align__(16) __nv_bfloat16 g_ksp_lo[(size_t)B_*H_*KSP_ROWS*DK_];
// projection inputs (bf16 split)
__device__ __align__(16) __nv_bfloat16 g_inq_hi[B_*L_*D_];
__device__ __align__(16) __nv_bfloat16 g_inq_lo[B_*L_*D_];
__device__ __align__(16) __nv_bfloat16 g_ink_hi[B_*L_*D_];
__device__ __align__(16) __nv_bfloat16 g_ink_lo[B_*L_*D_];
__device__ __align__(16) __nv_bfloat16 g_inv_hi[B_*L_*D_];
__device__ __align__(16) __nv_bfloat16 g_inv_lo[B_*L_*D_];
// weights (bf16 split): slots 0=Wq 1=Wk 2=Wv 3=Wproj
__device__ __align__(16) __nv_bfloat16 g_w_hi[4*D_*D_];
__device__ __align__(16) __nv_bfloat16 g_w_lo[4*D_*D_];
// v transposed per head: [z][n=0..63][k=0..1023]
__device__ __align__(16) __nv_bfloat16 g_vt_hi[(size_t)B_*H_*DK_*L_];
__device__ __align__(16) __nv_bfloat16 g_vt_lo[(size_t)B_*H_*DK_*L_];
// ctx in bf16 split, layout [B*L, 512]
__device__ __align__(16) __nv_bfloat16 g_ctx_hi[B_*L_*D_];
__device__ __align__(16) __nv_bfloat16 g_ctx_lo[B_*L_*D_];

// ====================== baseline-PTX tensor helpers ========================
static __device__ __forceinline__ uint32_t smem_u32(const void* p){
    uint32_t a;
    asm("{ .reg .u64 t; cvta.to.shared.u64 t, %1; cvt.u32.u64 %0, t; }"
        : "=r"(a) : "l"(p));
    return a;
}
#define CP_ASYNC16(dst, src) \
    asm volatile("cp.async.cg.shared.global [%0], [%1], 16;" \
                 :: "r"(dst), "l"(src) : "memory")
#define CP_COMMIT() asm volatile("cp.async.commit_group;" ::: "memory")
#define CP_WAIT(n)  asm volatile("cp.async.wait_group %0;" :: "n"(n) : "memory")
#define LDSM4(r0, r1, r2, r3, addr) \
    asm volatile("ldmatrix.sync.aligned.m8n8.x4.shared.b16 {%0,%1,%2,%3}, [%4];" \
                 : "=r"(r0), "=r"(r1), "=r"(r2), "=r"(r3) : "r"(addr))
#define MMA16816(d, a, b) \
    asm volatile("mma.sync.aligned.m16n8k16.row.col.f32.bf16.bf16.f32 " \
                 "{%0,%1,%2,%3},{%4,%5,%6,%7},{%8,%9},{%0,%1,%2,%3};" \
                 : "+f"((d)[0]), "+f"((d)[1]), "+f"((d)[2]), "+f"((d)[3]) \
                 : "r"((a)[0]), "r"((a)[1]), "r"((a)[2]), "r"((a)[3]), \
                   "r"((b)[0]), "r"((b)[1]))

static __device__ __forceinline__ unsigned pk2(float a, float b){
    __nv_bfloat162 t = __floats2bfloat162_rn(a, b);
    return *reinterpret_cast<unsigned*>(&t);
}
static __device__ __forceinline__ float bhi(float x){
    return __bfloat162float(__float2bfloat16_rn(x));
}

// ---------------------------------------------------------------------------
// conv_split3: fp32 -> bf16 hi/lo for q,k,v inputs in one launch (y = slot)
// ---------------------------------------------------------------------------
__global__ __launch_bounds__(256) void conv_split3_kernel(
    const float* __restrict__ s0, const float* __restrict__ s1,
    const float* __restrict__ s2, int n8)
{
    int i = blockIdx.x * 256 + threadIdx.x;
    if (i >= n8) return;
    const float* src; __nv_bfloat16 *dh, *dl;
    if (blockIdx.y == 0)      { src = s0; dh = g_inq_hi; dl = g_inq_lo; }
    else if (blockIdx.y == 1) { src = s1; dh = g_ink_hi; dl = g_ink_lo; }
    else                      { src = s2; dh = g_inv_hi; dl = g_inv_lo; }
    const float4* s = (const float4*)(src + (size_t)i * 8);
    float4 v0 = s[0], v1 = s[1];
    float f[8] = {v0.x, v0.y, v0.z, v0.w, v1.x, v1.y, v1.z, v1.w};
    float hh[8], ll[8];
#pragma unroll
    for (int e = 0; e < 8; e++) { hh[e] = bhi(f[e]); ll[e] = f[e] - hh[e]; }
    *(uint4*)(dh + (size_t)i * 8) = make_uint4(pk2(hh[0],hh[1]), pk2(hh[2],hh[3]),
                                               pk2(hh[4],hh[5]), pk2(hh[6],hh[7]));
    *(uint4*)(dl + (size_t)i * 8) = make_uint4(pk2(ll[0],ll[1]), pk2(ll[2],ll[3]),
                                               pk2(ll[4],ll[5]), pk2(ll[6],ll[7]));
}

// conv_split4: the 4 weight matrices into g_w slots (y = slot)
__global__ __launch_bounds__(256) void conv_split4_kernel(
    const float* __restrict__ s0, const float* __restrict__ s1,
    const float* __restrict__ s2, const float* __restrict__ s3, int n8)
{
    int i = blockIdx.x * 256 + threadIdx.x;
    if (i >= n8) return;
    const float* srcs[4] = {s0, s1, s2, s3};
    const float* src = srcs[blockIdx.y];
    size_t slot = (size_t)blockIdx.y * D_ * D_;
    const float4* s = (const float4*)(src + (size_t)i * 8);
    float4 v0 = s[0], v1 = s[1];
    float f[8] = {v0.x, v0.y, v0.z, v0.w, v1.x, v1.y, v1.z, v1.w};
    float hh[8], ll[8];
#pragma unroll
    for (int e = 0; e < 8; e++) { hh[e] = bhi(f[e]); ll[e] = f[e] - hh[e]; }
    *(uint4*)(g_w_hi + slot + (size_t)i * 8) =
        make_uint4(pk2(hh[0],hh[1]), pk2(hh[2],hh[3]),
                   pk2(hh[4],hh[5]), pk2(hh[6],hh[7]));
    *(uint4*)(g_w_lo + slot + (size_t)i * 8) =
        make_uint4(pk2(ll[0],ll[1]), pk2(ll[2],ll[3]),
                   pk2(ll[4],ll[5]), pk2(ll[6],ll[7]));
}

// ---------------------------------------------------------------------------
// Generic bf16x3 mma GEMM: C[M,N] = A@B^T + bias[N].  Tile 128x128.  (R6 ver)
// ---------------------------------------------------------------------------
#define GM_STAGE 32768
#define GM_SMEM  (2*GM_STAGE)

__global__ __launch_bounds__(256, 1) void gemm_mma_nt(
    const __nv_bfloat16* __restrict__ Ah, const __nv_bfloat16* __restrict__ Al,
    const __nv_bfloat16* __restrict__ Bh, const __nv_bfloat16* __restrict__ Bl,
    const float* __restrict__ bias, float* __restrict__ C, int K, int N)
{
    extern __shared__ char smem[];
    const uint32_t sbase = smem_u32(smem);
    const int kc = K >> 5;

    const int tid  = threadIdx.x;
    const int wid  = tid >> 5, lane = tid & 31;
    const int wm   = wid >> 2, wn = wid & 3;

    const int i0 = blockIdx.y * 128;
    const int j0 = blockIdx.x * 128;

    const __nv_bfloat16* ah = Ah + (size_t)i0 * K;
    const __nv_bfloat16* al = Al + (size_t)i0 * K;
    const __nv_bfloat16* bh_ = Bh + (size_t)j0 * K;
    const __nv_bfloat16* bl_ = Bl + (size_t)j0 * K;

    auto issue = [&](int s, int c) {
        const uint32_t sb = sbase + s * GM_STAGE;
#pragma unroll
        for (int q = 0; q < 4; q++) {
            int u  = q * 256 + tid;
            int r  = u >> 3, cj = u & 7;
            const __nv_bfloat16* src =
                (cj < 4 ? ah : al) + (size_t)r * K + c * 32 + (cj & 3) * 8;
            CP_ASYNC16(sb + r * 128 + 16 * (cj ^ (r & 7)), src);
        }
#pragma unroll
        for (int q = 0; q < 4; q++) {
            int u  = q * 256 + tid;
            int r  = u >> 3, cj = u & 7;
            const __nv_bfloat16* src =
                (cj < 4 ? bh_ : bl_) + (size_t)r * K + c * 32 + (cj & 3) * 8;
            CP_ASYNC16(sb + 16384 + r * 128 + 16 * (cj ^ (r & 7)), src);
        }
    };

    float acc[4][4][4];
#pragma unroll
    for (int i = 0; i < 4; i++)
#pragma unroll
        for (int j = 0; j < 4; j++)
#pragma unroll
            for (int e = 0; e < 4; e++) acc[i][j][e] = 0.f;

    issue(0, 0);
    CP_COMMIT();

    const int lrow = (lane & 7) + 8 * ((lane >> 3) & 1);
    const int lchk = lane >> 4;

    for (int c = 0; c < kc; c++) {
        const int s = c & 1;
        if (c + 1 < kc) { issue(s ^ 1, c + 1); CP_COMMIT(); CP_WAIT(1); }
        else            { CP_WAIT(0); }
        __syncthreads();

        const uint32_t sA = sbase + s * GM_STAGE;
        const uint32_t sB = sA + 16384;

#pragma unroll
        for (int ks = 0; ks < 2; ks++) {
            uint32_t bh[4][2], bl[4][2];
#pragma unroll
            for (int g = 0; g < 2; g++) {
                int r  = wn * 32 + g * 16 + lrow;
                int ch = ks * 2 + lchk;
                uint32_t r0, r1, r2, r3;
                LDSM4(r0, r1, r2, r3, sB + r * 128 + 16 * ((ch)     ^ (r & 7)));
                bh[2*g][0] = r0; bh[2*g][1] = r2;
                bh[2*g+1][0] = r1; bh[2*g+1][1] = r3;
                LDSM4(r0, r1, r2, r3, sB + r * 128 + 16 * ((ch + 4) ^ (r & 7)));
                bl[2*g][0] = r0; bl[2*g][1] = r2;
                bl[2*g+1][0] = r1; bl[2*g+1][1] = r3;
            }
#pragma unroll
            for (int mf = 0; mf < 4; mf++) {
                int r  = wm * 64 + mf * 16 + lrow;
                int ch = ks * 2 + lchk;
                uint32_t ah_[4], al_[4];
                LDSM4(ah_[0], ah_[1], ah_[2], ah_[3],
                      sA + r * 128 + 16 * ((ch)     ^ (r & 7)));
                LDSM4(al_[0], al_[1], al_[2], al_[3],
                      sA + r * 128 + 16 * ((ch + 4) ^ (r & 7)));
#pragma unroll
                for (int nf = 0; nf < 4; nf++) {
                    MMA16816(acc[mf][nf], ah_, bh[nf]);
                    MMA16816(acc[mf][nf], ah_, bl[nf]);
                    MMA16816(acc[mf][nf], al_, bh[nf]);
                }
            }
        }
        __syncthreads();
    }

    const int rbase = i0 + wm * 64 + (lane >> 2);
    const int cbase = j0 + wn * 32 + 2 * (lane & 3);
#pragma unroll
    for (int mf = 0; mf < 4; mf++) {
        int gi = rbase + mf * 16;
        float* row0 = C + (size_t)gi * N;
        float* row1 = row0 + 8 * N;
#pragma unroll
        for (int nf = 0; nf < 4; nf++) {
            int gj = cbase + nf * 8;
            float b0 = bias[gj], b1 = bias[gj + 1];
            *(float2*)(row0 + gj) = make_float2(acc[mf][nf][0] + b0,
                                                acc[mf][nf][1] + b1);
            *(float2*)(row1 + gj) = make_float2(acc[mf][nf][2] + b0,
                                                acc[mf][nf][3] + b1);
        }
    }
}

// ---------------------------------------------------------------------------
// bcat[h, t*64+c] = bker[h,c,t]
// ---------------------------------------------------------------------------
__global__ void bcat_kernel(const float* __restrict__ bker)
{
    int n = blockIdx.x * blockDim.x + threadIdx.x;
    if (n >= H_ * NCAT) return;
    int h = n / NCAT, r = n % NCAT, t = r / DK_, c = r % DK_;
    g_bcat[n] = bker[(size_t)(h*DK_ + c) * KW_ + t];
}

// ---------------------------------------------------------------------------
// Qcat (fp32 SIMT, R6-proven): per (b,h):
//   Qcat[i, n=t*64+c] = sum_d q_s[i,d]*Wker[h,c,t,d] + bcat.  bf16 hi/lo out.
// grid (4, 8, 64)
// ---------------------------------------------------------------------------
__global__ __launch_bounds__(256) void qcat_kernel(const float* __restrict__ Wker)
{
    const int z = blockIdx.z;
    const int b = z >> 3, h = z & 7;
    const int bm = blockIdx.y * 128;
    const int bn = blockIdx.x * 128;
    const int tid = threadIdx.x;
    const int ty = tid >> 4, tx = tid & 15;

    __shared__ float As[16][128];
    __shared__ float Bs[16][128];

    const float* A = g_qs + (size_t)b * L_ * D_ + h * DK_;
    const float* W = Wker + (size_t)h * DK_ * NCAT;

    float acc[8][8];
#pragma unroll
    for (int i = 0; i < 8; i++)
#pragma unroll
        for (int j = 0; j < 8; j++) acc[i][j] = 0.f;

    const int lr = tid >> 2, lc = (tid & 3) << 2;

    for (int k0 = 0; k0 < DK_; k0 += 16) {
#pragma unroll
        for (int s = 0; s < 2; s++) {
            int row = lr + s * 64;
            float4 va = *(const float4*)(A + (size_t)(bm + row) * D_ + k0 + lc);
            As[lc+0][row] = va.x; As[lc+1][row] = va.y;
            As[lc+2][row] = va.z; As[lc+3][row] = va.w;
        }
        for (int idx = tid; idx < 512; idx += 256) {
            int nloc = idx >> 2;
            int kl   = (idx & 3) << 2;
            int gn = bn + nloc;
            float4 vb = make_float4(0,0,0,0);
            if (gn < NCAT) {
                int t = gn >> 6, c = gn & 63;
                vb = *(const float4*)(W + (size_t)c * NCAT + t * DK_ + k0 + kl);
            }
            Bs[kl+0][nloc] = vb.x; Bs[kl+1][nloc] = vb.y;
            Bs[kl+2][nloc] = vb.z; Bs[kl+3][nloc] = vb.w;
        }
        __syncthreads();
#pragma unroll
        for (int kk = 0; kk < 16; kk++) {
            float ra[8], rb[8];
            *(float4*)(ra)   = *(const float4*)&As[kk][ty*8];
            *(float4*)(ra+4) = *(const float4*)&As[kk][ty*8+4];
            *(float4*)(rb)   = *(const float4*)&Bs[kk][tx*4];
            *(float4*)(rb+4) = *(const float4*)&Bs[kk][64 + tx*4];
#pragma unroll
            for (int i = 0; i < 8; i++)
#pragma unroll
                for (int j = 0; j < 8; j++)
                    acc[i][j] = fmaf(ra[i], rb[j], acc[i][j]);
        }
        __syncthreads();
    }

    __nv_bfloat16* Ch = g_qcat_hi + (size_t)z * L_ * NCAT;
    __nv_bfloat16* Cl = g_qcat_lo + (size_t)z * L_ * NCAT;
    int c0g = bn + tx*4, c1g = bn + 64 + tx*4;
    float4 b0 = make_float4(0,0,0,0), b1 = make_float4(0,0,0,0);
    if (c0g < NCAT) b0 = *(const float4*)(g_bcat + h*NCAT + c0g);
    if (c1g < NCAT) b1 = *(const float4*)(g_bcat + h*NCAT + c1g);
#pragma unroll
    for (int i = 0; i < 8; i++) {
        size_t ro = (size_t)(bm + ty*8 + i) * NCAT;
        if (c0g < NCAT) {
            float v0 = acc[i][0]+b0.x, v1 = acc[i][1]+b0.y;
            float v2 = acc[i][2]+b0.z, v3 = acc[i][3]+b0.w;
            float h0 = bhi(v0), h1 = bhi(v1), h2 = bhi(v2), h3 = bhi(v3);
            *(uint2*)(Ch + ro + c0g) = make_uint2(pk2(h0,h1), pk2(h2,h3));
            *(uint2*)(Cl + ro + c0g) = make_uint2(pk2(v0-h0,v1-h1), pk2(v2-h2,v3-h3));
        }
        if (c1g < NCAT) {
            float v0 = acc[i][4]+b1.x, v1 = acc[i][5]+b1.y;
            float v2 = acc[i][6]+b1.z, v3 = acc[i][7]+b1.w;
            float h0 = bhi(v0), h1 = bhi(v1), h2 = bhi(v2), h3 = bhi(v3);
            *(uint2*)(Ch + ro + c1g) = make_uint2(pk2(h0,h1), pk2(h2,h3));
            *(uint2*)(Cl + ro + c1g) = make_uint2(pk2(v0-h0,v1-h1), pk2(v2-h2,v3-h3));
        }
    }
}

// ---------------------------------------------------------------------------
// ks_pad prep: g_ksp[z][j+3][c] = split(k_s[b][j][h*64+c]); pad rows zero.
// ---------------------------------------------------------------------------
__global__ __launch_bounds__(256) void ksp_prep_kernel()
{
    int idx = blockIdx.x * 256 + threadIdx.x;      // over 64*1030*8
    if (idx >= B_*H_*KSP_ROWS*8) return;
    int c8  = (idx & 7) * 8;
    int row = (idx >> 3) % KSP_ROWS;
    int z   = (idx >> 3) / KSP_ROWS;
    int b = z >> 3, h = z & 7;
    int j = row - PAD_;
    float f[8] = {0,0,0,0,0,0,0,0};
    if (j >= 0 && j < L_) {
        const float* p = g_ks + ((size_t)(b*L_ + j)) * D_ + h*DK_ + c8;
        float4 v0 = *(const float4*)p, v1 = *(const float4*)(p + 4);
        f[0]=v0.x; f[1]=v0.y; f[2]=v0.z; f[3]=v0.w;
        f[4]=v1.x; f[5]=v1.y; f[6]=v1.z; f[7]=v1.w;
    }
    float hh[8], ll[8];
#pragma unroll
    for (int e = 0; e < 8; e++) { hh[e] = bhi(f[e]); ll[e] = f[e] - hh[e]; }
    size_t off = ((size_t)z * KSP_ROWS + row) * DK_ + c8;
    *(uint4*)(g_ksp_hi + off) = make_uint4(pk2(hh[0],hh[1]), pk2(hh[2],hh[3]),
                                           pk2(hh[4],hh[5]), pk2(hh[6],hh[7]));
    *(uint4*)(g_ksp_lo + off) = make_uint4(pk2(ll[0],ll[1]), pk2(ll[2],ll[3]),
                                           pk2(ll[4],ll[5]), pk2(ll[6],ll[7]));
}

// ---------------------------------------------------------------------------
// Logits: 128x128 tile, K=448 in 14 chunks of 32.  B direct from padded k_s:
// chunk c -> t = c>>1, cols (c&1)*32..+31, B row = j0 + r + t.
// No rowbias (row-constant terms cancel in softmax).  grid (8, 8, 64).
// ---------------------------------------------------------------------------
#define LOG_STAGE 32768
#define LOG_SMEM  (2*LOG_STAGE)

__global__ __launch_bounds__(256, 1) void logits_mma_kernel(float* __restrict__ attn)
{
    extern __shared__ char smem[];
    const uint32_t sbase = smem_u32(smem);

    const int tid  = threadIdx.x;
    const int wid  = tid >> 5, lane = tid & 31;
    const int wm   = wid >> 2, wn = wid & 3;

    const int z  = blockIdx.z;
    const int i0 = blockIdx.y * 128;
    const int j0 = blockIdx.x * 128;

    const __nv_bfloat16* qh = g_qcat_hi + (size_t)z * L_ * NCAT + (size_t)i0 * NCAT;
    const __nv_bfloat16* ql = g_qcat_lo + (size_t)z * L_ * NCAT + (size_t)i0 * NCAT;
    const __nv_bfloat16* ksh = g_ksp_hi + (size_t)z * KSP_ROWS * DK_;
    const __nv_bfloat16* ksl = g_ksp_lo + (size_t)z * KSP_ROWS * DK_;

    auto issue = [&](int s, int c) {
        const uint32_t sb = sbase + s * LOG_STAGE;
        const int t = c >> 1, colb = (c & 1) * 32;
#pragma unroll
        for (int q = 0; q < 4; q++) {          // A: 128 rows x 128B
            int u  = q * 256 + tid;
            int r  = u >> 3, cj = u & 7;
            const __nv_bfloat16* src =
                (cj < 4 ? qh : ql) + (size_t)r * NCAT + c * 32 + (cj & 3) * 8;
            CP_ASYNC16(sb + r * 128 + 16 * (cj ^ (r & 7)), src);
        }
#pragma unroll
        for (int q = 0; q < 4; q++) {          // B: 128 rows x 128B
            int u  = q * 256 + tid;
            int r  = u >> 3, cj = u & 7;
            const __nv_bfloat16* src =
                (cj < 4 ? ksh : ksl) + (size_t)(j0 + r + t) * DK_ + colb + (cj & 3) * 8;
            CP_ASYNC16(sb + 16384 + r * 128 + 16 * (cj ^ (r & 7)), src);
        }
    };

    float acc[4][4][4];
#pragma unroll
    for (int i = 0; i < 4; i++)
#pragma unroll
        for (int j = 0; j < 4; j++)
#pragma unroll
            for (int e = 0; e < 4; e++) acc[i][j][e] = 0.f;

    issue(0, 0);
    CP_COMMIT();

    const int lrow = (lane & 7) + 8 * ((lane >> 3) & 1);
    const int lchk = lane >> 4;

    for (int c = 0; c < 14; c++) {
        const int s = c & 1;
        if (c + 1 < 14) { issue(s ^ 1, c + 1); CP_COMMIT(); CP_WAIT(1); }
        else            { CP_WAIT(0); }
        __syncthreads();

        const uint32_t sA = sbase + s * LOG_STAGE;
        const uint32_t sB = sA + 16384;

#pragma unroll
        for (int ks = 0; ks < 2; ks++) {
            uint32_t bh[4][2], bl[4][2];
#pragma unroll
            for (int g = 0; g < 2; g++) {
                int r  = wn * 32 + g * 16 + lrow;
                int ch = ks * 2 + lchk;
                uint32_t r0, r1, r2, r3;
                LDSM4(r0, r1, r2, r3, sB + r * 128 + 16 * ((ch)     ^ (r & 7)));
                bh[2*g][0] = r0; bh[2*g][1] = r2;
                bh[2*g+1][0] = r1; bh[2*g+1][1] = r3;
                LDSM4(r0, r1, r2, r3, sB + r * 128 + 16 * ((ch + 4) ^ (r & 7)));
                bl[2*g][0] = r0; bl[2*g][1] = r2;
                bl[2*g+1][0] = r1; bl[2*g+1][1] = r3;
            }
#pragma unroll
            for (int mf = 0; mf < 4; mf++) {
                int r  = wm * 64 + mf * 16 + lrow;
                int ch = ks * 2 + lchk;
                uint32_t ah[4], al[4];
                LDSM4(ah[0], ah[1], ah[2], ah[3],
                      sA + r * 128 + 16 * ((ch)     ^ (r & 7)));
                LDSM4(al[0], al[1], al[2], al[3],
                      sA + r * 128 + 16 * ((ch + 4) ^ (r & 7)));
#pragma unroll
                for (int nf = 0; nf < 4; nf++) {
                    MMA16816(acc[mf][nf], ah, bh[nf]);
                    MMA16816(acc[mf][nf], ah, bl[nf]);
                    MMA16816(acc[mf][nf], al, bh[nf]);
                }
            }
        }
        __syncthreads();
    }

    const int rbase = i0 + wm * 64 + (lane >> 2);
    const int cbase = j0 + wn * 32 + 2 * (lane & 3);
#pragma unroll
    for (int mf = 0; mf < 4; mf++) {
        int gi0 = rbase + mf * 16;
        float* row0 = attn + ((size_t)z * L_ + gi0) * L_;
        float* row1 = row0 + 8 * L_;
#pragma unroll
        for (int nf = 0; nf < 4; nf++) {
            int gj = cbase + nf * 8;
            *(float2*)(row0 + gj) = make_float2(acc[mf][nf][0]*0.125f,
                                                acc[mf][nf][1]*0.125f);
            *(float2*)(row1 + gj) = make_float2(acc[mf][nf][2]*0.125f,
                                                acc[mf][nf][3]*0.125f);
        }
    }
}

// ---------------------------------------------------------------------------
// Row softmax in-place on attn; mask; head-0 duplicate.
// (logits carry no rowbias — row-constant shift cancels in softmax)
// ---------------------------------------------------------------------------
__global__ __launch_bounds__(256) void softmax_kernel(
    float* __restrict__ attn, const unsigned char* __restrict__ mask,
    float* __restrict__ one_head)
{
    const int r = blockIdx.x;
    const int i = r & (L_-1);
    const int bh = r >> 10;
    const int h = bh & (H_-1), b = bh >> 3;
    float* row = attn + (size_t)r * L_;
    const unsigned char* mrow = mask + ((size_t)(b*L_ + i)) * L_;
    const int t4 = threadIdx.x * 4;

    float4 v = *(const float4*)(row + t4);
    uchar4 m = *(const uchar4*)(mrow + t4);
    float x0 = m.x ? -INFINITY : v.x;
    float x1 = m.y ? -INFINITY : v.y;
    float x2 = m.z ? -INFINITY : v.z;
    float x3 = m.w ? -INFINITY : v.w;

    __shared__ float sm[8], ss[8];
    float mx = fmaxf(fmaxf(x0, x1), fmaxf(x2, x3));
#pragma unroll
    for (int o = 16; o; o >>= 1) mx = fmaxf(mx, __shfl_xor_sync(0xffffffffu, mx, o));
    if ((threadIdx.x & 31) == 0) sm[threadIdx.x >> 5] = mx;
    __syncthreads();
    if (threadIdx.x < 32) {
        float t = (threadIdx.x < 8) ? sm[threadIdx.x] : -INFINITY;
#pragma unroll
        for (int o = 4; o; o >>= 1) t = fmaxf(t, __shfl_xor_sync(0xffffffffu, t, o));
        if (threadIdx.x == 0) sm[0] = t;
    }
    __syncthreads();
    mx = sm[0];

    float e0 = __expf(x0 - mx), e1 = __expf(x1 - mx);
    float e2 = __expf(x2 - mx), e3 = __expf(x3 - mx);
    float s = (e0 + e1) + (e2 + e3);
#pragma unroll
    for (int o = 16; o; o >>= 1) s += __shfl_xor_sync(0xffffffffu, s, o);
    if ((threadIdx.x & 31) == 0) ss[threadIdx.x >> 5] = s;
    __syncthreads();
    if (threadIdx.x < 32) {
        float t = (threadIdx.x < 8) ? ss[threadIdx.x] : 0.f;
#pragma unroll
        for (int o = 4; o; o >>= 1) t += __shfl_xor_sync(0xffffffffu, t, o);
        if (threadIdx.x == 0) ss[0] = t;
    }
    __syncthreads();
    float inv = 1.0f / ss[0];

    float4 o = make_float4(e0*inv, e1*inv, e2*inv, e3*inv);
    *(float4*)(row + t4) = o;
    if (h == 0)
        *(float4*)(one_head + ((size_t)(b*L_ + i)) * L_ + t4) = o;
}

// ---------------------------------------------------------------------------
// vt transpose: vt[z][n][k] = v_s[b][k][h*64+n], bf16 hi/lo.
// ---------------------------------------------------------------------------
__global__ __launch_bounds__(256) void vt_kernel()
{
    __shared__ float t[128][65];
    const int z = blockIdx.y;
    const int b = z >> 3, h = z & 7;
    const int k0 = blockIdx.x * 128;
    const int tid = threadIdx.x;

#pragma unroll
    for (int q = 0; q < 8; q++) {
        int u = q * 256 + tid;
        int r = u >> 4, c4 = (u & 15) * 4;
        float4 v = *(const float4*)(g_vs + ((size_t)(b*L_ + k0 + r)) * D_ + h*DK_ + c4);
        t[r][c4+0] = v.x; t[r][c4+1] = v.y; t[r][c4+2] = v.z; t[r][c4+3] = v.w;
    }
    __syncthreads();

#pragma unroll
    for (int q = 0; q < 4; q++) {
        int u = q * 256 + tid;
        int n = u >> 4, kk = (u & 15) * 8;
        float f[8], hh[8], ll[8];
#pragma unroll
        for (int e = 0; e < 8; e++) f[e] = t[kk + e][n];
#pragma unroll
        for (int e = 0; e < 8; e++) { hh[e] = bhi(f[e]); ll[e] = f[e] - hh[e]; }
        size_t off = (size_t)z * DK_ * L_ + (size_t)n * L_ + k0 + kk;
        *(uint4*)(g_vt_hi + off) = make_uint4(pk2(hh[0],hh[1]), pk2(hh[2],hh[3]),
                                              pk2(hh[4],hh[5]), pk2(hh[6],hh[7]));
        *(uint4*)(g_vt_lo + off) = make_uint4(pk2(ll[0],ll[1]), pk2(ll[2],ll[3]),
                                              pk2(ll[4],ll[5]), pk2(ll[6],ll[7]));
    }
}

// ---------------------------------------------------------------------------
// ctx via mma: per (b,h): C[1024,64] = attn @ v_head.  (R6 version)
// ---------------------------------------------------------------------------
#define CTX_STAGE 24576

__global__ __launch_bounds__(256, 1) void ctx_mma_kernel(const float* __restrict__ attn)
{
    __shared__ char smem[2 * CTX_STAGE];
    const uint32_t sbase = smem_u32(smem);

    const int tid  = threadIdx.x;
    const int wid  = tid >> 5, lane = tid & 31;
    const int wm   = wid >> 2, wn = wid & 3;

    const int z  = blockIdx.y;
    const int b = z >> 3, h = z & 7;
    const int i0 = blockIdx.x * 128;

    const float* A = attn + ((size_t)z * L_ + i0) * L_;
    const __nv_bfloat16* vh = g_vt_hi + (size_t)z * DK_ * L_;
    const __nv_bfloat16* vl = g_vt_lo + (size_t)z * DK_ * L_;

    auto issueB = [&](int s, int c) {
        const uint32_t sb = sbase + s * CTX_STAGE + 16384;
#pragma unroll
        for (int q = 0; q < 2; q++) {
            int u  = q * 256 + tid;
            int r  = u >> 3, cj = u & 7;
            const __nv_bfloat16* src =
                (cj < 4 ? vh : vl) + (size_t)r * L_ + c * 32 + (cj & 3) * 8;
            CP_ASYNC16(sb + r * 128 + 16 * (cj ^ (r & 7)), src);
        }
    };
    float fa[2][8];
    auto ldgA = [&](int c) {
#pragma unroll
        for (int q = 0; q < 2; q++) {
            int u = q * 256 + tid;
            int r = u >> 2, seg = u & 3;
            const float4* p = (const float4*)(A + (size_t)r * L_ + c * 32 + seg * 8);
            float4 v0 = p[0], v1 = p[1];
            fa[q][0]=v0.x; fa[q][1]=v0.y; fa[q][2]=v0.z; fa[q][3]=v0.w;
            fa[q][4]=v1.x; fa[q][5]=v1.y; fa[q][6]=v1.z; fa[q][7]=v1.w;
        }
    };
    auto stsA = [&](int s) {
#pragma unroll
        for (int q = 0; q < 2; q++) {
            int u = q * 256 + tid;
            int r = u >> 2, seg = u & 3;
            float hh[8], ll[8];
#pragma unroll
            for (int e = 0; e < 8; e++) { hh[e] = bhi(fa[q][e]); ll[e] = fa[q][e] - hh[e]; }
            *(uint4*)(smem + s * CTX_STAGE + r * 128 + 16 * ((seg)     ^ (r & 7))) =
                make_uint4(pk2(hh[0],hh[1]), pk2(hh[2],hh[3]),
                           pk2(hh[4],hh[5]), pk2(hh[6],hh[7]));
            *(uint4*)(smem + s * CTX_STAGE + r * 128 + 16 * ((seg + 4) ^ (r & 7))) =
                make_uint4(pk2(ll[0],ll[1]), pk2(ll[2],ll[3]),
                           pk2(ll[4],ll[5]), pk2(ll[6],ll[7]));
        }
    };

    float acc[4][2][4];
#pragma unroll
    for (int i = 0; i < 4; i++)
#pragma unroll
        for (int j = 0; j < 2; j++)
#pragma unroll
            for (int e = 0; e < 4; e++) acc[i][j][e] = 0.f;

    ldgA(0);
    issueB(0, 0); CP_COMMIT();

    const int lrow = (lane & 7) + 8 * ((lane >> 3) & 1);
    const int lchk = lane >> 4;

    for (int c = 0; c < 32; c++) {
        const int s = c & 1;
        stsA(s);
        if (c + 1 < 32) {
            ldgA(c + 1);
            issueB(s ^ 1, c + 1); CP_COMMIT(); CP_WAIT(1);
        } else {
            CP_WAIT(0);
        }
        __syncthreads();

        const uint32_t sA = sbase + s * CTX_STAGE;
        const uint32_t sB = sA + 16384;

#pragma unroll
        for (int ks = 0; ks < 2; ks++) {
            uint32_t bh[2][2], bl[2][2];
            {
                int r  = wn * 16 + lrow;
                int ch = ks * 2 + lchk;
                uint32_t r0, r1, r2, r3;
                LDSM4(r0, r1, r2, r3, sB + r * 128 + 16 * ((ch)     ^ (r & 7)));
                bh[0][0] = r0; bh[0][1] = r2; bh[1][0] = r1; bh[1][1] = r3;
                LDSM4(r0, r1, r2, r3, sB + r * 128 + 16 * ((ch + 4) ^ (r & 7)));
                bl[0][0] = r0; bl[0][1] = r2; bl[1][0] = r1; bl[1][1] = r3;
            }
#pragma unroll
            for (int mf = 0; mf < 4; mf++) {
                int r  = wm * 64 + mf * 16 + lrow;
                int ch = ks * 2 + lchk;
                uint32_t ah[4], al[4];
                LDSM4(ah[0], ah[1], ah[2], ah[3],
                      sA + r * 128 + 16 * ((ch)     ^ (r & 7)));
                LDSM4(al[0], al[1], al[2], al[3],
                      sA + r * 128 + 16 * ((ch + 4) ^ (r & 7)));
#pragma unroll
                for (int nf = 0; nf < 2; nf++) {
                    MMA16816(acc[mf][nf], ah, bh[nf]);
                    MMA16816(acc[mf][nf], ah, bl[nf]);
                    MMA16816(acc[mf][nf], al, bh[nf]);
                }
            }
        }
        __syncthreads();
    }

    const int rbase = i0 + wm * 64 + (lane >> 2);
    const int cb = h * DK_ + wn * 16 + 2 * (lane & 3);
#pragma unroll
    for (int mf = 0; mf < 4; mf++) {
        int gi = rbase + mf * 16;
        size_t ro0 = ((size_t)(b * L_) + gi) * D_;
        size_t ro1 = ro0 + 8 * D_;
#pragma unroll
        for (int nf = 0; nf < 2; nf++) {
            int gj = cb + nf * 8;
            float v0 = acc[mf][nf][0], v1 = acc[mf][nf][1];
            float v2 = acc[mf][nf][2], v3 = acc[mf][nf][3];
            float h0 = bhi(v0), h1 = bhi(v1), h2 = bhi(v2), h3 = bhi(v3);
            *(unsigned*)(g_ctx_hi + ro0 + gj) = pk2(h0, h1);
            *(unsigned*)(g_ctx_lo + ro0 + gj) = pk2(v0 - h0, v1 - h1);
            *(unsigned*)(g_ctx_hi + ro1 + gj) = pk2(h2, h3);
            *(unsigned*)(g_ctx_lo + ro1 + gj) = pk2(v2 - h2, v3 - h3);
        }
    }
}

// ---------------------------------------------------------------------------
extern "C" void kernel_launch(void* const* d_in, const int* in_sizes, int n_in,
                              void* d_out, int out_size)
{
    const float* q      = (const float*)d_in[0];
    const float* k      = (const float*)d_in[1];
    const float* v      = (const float*)d_in[2];
    const unsigned char* mask = (const unsigned char*)d_in[3];
    const float* Wq     = (const float*)d_in[4];
    const float* bq     = (const float*)d_in[5];
    const float* Wk     = (const float*)d_in[6];
    const float* bk     = (const float*)d_in[7];
    const float* Wv     = (const float*)d_in[8];
    const float* bv     = (const float*)d_in[9];
    const float* Wker   = (const float*)d_in[10];
    const float* bker   = (const float*)d_in[11];
    const float* Wproj  = (const float*)d_in[15];
    const float* bproj  = (const float*)d_in[16];

    float* out      = (float*)d_out;
    float* attn     = out + (size_t)B_ * L_ * D_;
    float* one_head = attn + (size_t)B_ * H_ * L_ * L_;

    void* p;
    cudaGetSymbolAddress(&p, g_qs);  float* qs  = (float*)p;
    cudaGetSymbolAddress(&p, g_ks);  float* ks  = (float*)p;
    cudaGetSymbolAddress(&p, g_vs);  float* vs  = (float*)p;
    __nv_bfloat16 *iqh, *iql, *ikh, *ikl, *ivh, *ivl, *wh, *wl, *ch, *cl;
    cudaGetSymbolAddress(&p, g_inq_hi); iqh = (__nv_bfloat16*)p;
    cudaGetSymbolAddress(&p, g_inq_lo); iql = (__nv_bfloat16*)p;
    cudaGetSymbolAddress(&p, g_ink_hi); ikh = (__nv_bfloat16*)p;
    cudaGetSymbolAddress(&p, g_ink_lo); ikl = (__nv_bfloat16*)p;
    cudaGetSymbolAddress(&p, g_inv_hi); ivh = (__nv_bfloat16*)p;
    cudaGetSymbolAddress(&p, g_inv_lo); ivl = (__nv_bfloat16*)p;
    cudaGetSymbolAddress(&p, g_w_hi);   wh  = (__nv_bfloat16*)p;
    cudaGetSymbolAddress(&p, g_w_lo);   wl  = (__nv_bfloat16*)p;
    cudaGetSymbolAddress(&p, g_ctx_hi); ch  = (__nv_bfloat16*)p;
    cudaGetSymbolAddress(&p, g_ctx_lo); cl  = (__nv_bfloat16*)p;

    static bool attr_done = false;
    if (!attr_done) {
        cudaFuncSetAttribute(logits_mma_kernel,
            cudaFuncAttributeMaxDynamicSharedMemorySize, LOG_SMEM);
        cudaFuncSetAttribute(gemm_mma_nt,
            cudaFuncAttributeMaxDynamicSharedMemorySize, GM_SMEM);
        attr_done = true;
    }

    const int M = B_ * L_;        // 8192
    const int NE = M * D_;
    const int NW = D_ * D_;
    dim3 blk(256);

    // 0) splits + weight prep (fused launches)
    conv_split3_kernel<<<dim3((NE/8 + 255)/256, 3), 256>>>(q, k, v, NE/8);
    conv_split4_kernel<<<dim3((NW/8 + 255)/256, 4), 256>>>(Wq, Wk, Wv, Wproj, NW/8);
    bcat_kernel<<<(H_*NCAT + 255)/256, 256>>>(bker);

    // 1) projections (tensor cores)
    gemm_mma_nt<<<dim3(D_/128, M/128), blk, GM_SMEM>>>(iqh, iql, wh,        wl,        bq, qs, D_, D_);
    gemm_mma_nt<<<dim3(D_/128, M/128), blk, GM_SMEM>>>(ikh, ikl, wh + NW,   wl + NW,   bk, ks, D_, D_);
    gemm_mma_nt<<<dim3(D_/128, M/128), blk, GM_SMEM>>>(ivh, ivl, wh + 2*NW, wl + 2*NW, bv, vs, D_, D_);

    // 2) operand prep
    qcat_kernel<<<dim3(4, L_/128, B_*H_), blk>>>(Wker);
    ksp_prep_kernel<<<(B_*H_*KSP_ROWS*8 + 255)/256, 256>>>();
    vt_kernel<<<dim3(L_/128, B_*H_), blk>>>();

    // 3) tensor-core logits -> attn region (raw, scaled; no rowbias)
    logits_mma_kernel<<<dim3(L_/128, L_/128, B_*H_), 256, LOG_SMEM>>>(attn);

    // 4) softmax in place (+ one_head copy)
    softmax_kernel<<<B_*H_*L_, 256>>>(attn, mask, one_head);

    // 5) ctx = attn @ v_s -> g_ctx hi/lo
    ctx_mma_kernel<<<dim3(L_/128, B_*H_), blk>>>(attn);

    // 6) out = ctx @ Wproj^T + bproj
    gemm_mma_nt<<<dim3(D_/128, M/128), blk, GM_SMEM>>>(ch, cl, wh + 3*NW, wl + 3*NW, bproj, out, D_, D_);
}

// round 10
// speedup vs baseline: 1.0956x; 1.0956x over previous
#include <cuda_runtime.h>
#include <cuda_bf16.h>
#include <cstdint>

#define B_   8
#define L_   1024
#define D_   512
#define H_   8
#define DK_  64
#define KW_  7
#define PAD_ 3
#define NCAT 448    /* KW*DK */

// ---------------- scratch (device globals; no runtime allocation) ----------
__device__ float g_qs[B_*L_*D_];
__device__ float g_ks[B_*L_*D_];
__device__ float g_vs[B_*L_*D_];
__device__ float g_bcat[H_*NCAT];
// bf16 hi/lo operands for the logits GEMM
__device__ __align__(16) __nv_bfloat16 g_qcat_hi[(size_t)B_*H_*L_*NCAT];
__device__ __align__(16) __nv_bfloat16 g_qcat_lo[(size_t)B_*H_*L_*NCAT];
__device__ __align__(16) __nv_bfloat16 g_kcat_hi[(size_t)B_*H_*L_*NCAT];
__device__ __align__(16) __nv_bfloat16 g_kcat_lo[(size_t)B_*H_*L_*NCAT];
// projection inputs (bf16 split)
__device__ __align__(16) __nv_bfloat16 g_inq_hi[B_*L_*D_];
__device__ __align__(16) __nv_bfloat16 g_inq_lo[B_*L_*D_];
__device__ __align__(16) __nv_bfloat16 g_ink_hi[B_*L_*D_];
__device__ __align__(16) __nv_bfloat16 g_ink_lo[B_*L_*D_];
__device__ __align__(16) __nv_bfloat16 g_inv_hi[B_*L_*D_];
__device__ __align__(16) __nv_bfloat16 g_inv_lo[B_*L_*D_];
// weights (bf16 split): slots 0=Wq 1=Wk 2=Wv 3=Wproj
__device__ __align__(16) __nv_bfloat16 g_w_hi[4*D_*D_];
__device__ __align__(16) __nv_bfloat16 g_w_lo[4*D_*D_];
// v transposed per head: [z][n=0..63][k=0..1023]
__device__ __align__(16) __nv_bfloat16 g_vt_hi[(size_t)B_*H_*DK_*L_];
__device__ __align__(16) __nv_bfloat16 g_vt_lo[(size_t)B_*H_*DK_*L_];
// ctx in bf16 split, layout [B*L, 512]
__device__ __align__(16) __nv_bfloat16 g_ctx_hi[B_*L_*D_];
__device__ __align__(16) __nv_bfloat16 g_ctx_lo[B_*L_*D_];

// ====================== baseline-PTX tensor helpers ========================
static __device__ __forceinline__ uint32_t smem_u32(const void* p){
    uint32_t a;
    asm("{ .reg .u64 t; cvta.to.shared.u64 t, %1; cvt.u32.u64 %0, t; }"
        : "=r"(a) : "l"(p));
    return a;
}
#define CP_ASYNC16(dst, src) \
    asm volatile("cp.async.cg.shared.global [%0], [%1], 16;" \
                 :: "r"(dst), "l"(src) : "memory")
#define CP_COMMIT() asm volatile("cp.async.commit_group;" ::: "memory")
#define CP_WAIT(n)  asm volatile("cp.async.wait_group %0;" :: "n"(n) : "memory")
#define LDSM4(r0, r1, r2, r3, addr) \
    asm volatile("ldmatrix.sync.aligned.m8n8.x4.shared.b16 {%0,%1,%2,%3}, [%4];" \
                 : "=r"(r0), "=r"(r1), "=r"(r2), "=r"(r3) : "r"(addr))
#define MMA16816(d, a, b) \
    asm volatile("mma.sync.aligned.m16n8k16.row.col.f32.bf16.bf16.f32 " \
                 "{%0,%1,%2,%3},{%4,%5,%6,%7},{%8,%9},{%0,%1,%2,%3};" \
                 : "+f"((d)[0]), "+f"((d)[1]), "+f"((d)[2]), "+f"((d)[3]) \
                 : "r"((a)[0]), "r"((a)[1]), "r"((a)[2]), "r"((a)[3]), \
                   "r"((b)[0]), "r"((b)[1]))

static __device__ __forceinline__ unsigned pk2(float a, float b){
    __nv_bfloat162 t = __floats2bfloat162_rn(a, b);
    return *reinterpret_cast<unsigned*>(&t);
}
static __device__ __forceinline__ float bhi(float x){
    return __bfloat162float(__float2bfloat16_rn(x));
}

// ---------------------------------------------------------------------------
// conv_split3: fp32 -> bf16 hi/lo for q,k,v inputs in one launch (y = slot)
// ---------------------------------------------------------------------------
__global__ __launch_bounds__(256) void conv_split3_kernel(
    const float* __restrict__ s0, const float* __restrict__ s1,
    const float* __restrict__ s2, int n8)
{
    int i = blockIdx.x * 256 + threadIdx.x;
    if (i >= n8) return;
    const float* src; __nv_bfloat16 *dh, *dl;
    if (blockIdx.y == 0)      { src = s0; dh = g_inq_hi; dl = g_inq_lo; }
    else if (blockIdx.y == 1) { src = s1; dh = g_ink_hi; dl = g_ink_lo; }
    else                      { src = s2; dh = g_inv_hi; dl = g_inv_lo; }
    const float4* s = (const float4*)(src + (size_t)i * 8);
    float4 v0 = s[0], v1 = s[1];
    float f[8] = {v0.x, v0.y, v0.z, v0.w, v1.x, v1.y, v1.z, v1.w};
    float hh[8], ll[8];
#pragma unroll
    for (int e = 0; e < 8; e++) { hh[e] = bhi(f[e]); ll[e] = f[e] - hh[e]; }
    *(uint4*)(dh + (size_t)i * 8) = make_uint4(pk2(hh[0],hh[1]), pk2(hh[2],hh[3]),
                                               pk2(hh[4],hh[5]), pk2(hh[6],hh[7]));
    *(uint4*)(dl + (size_t)i * 8) = make_uint4(pk2(ll[0],ll[1]), pk2(ll[2],ll[3]),
                                               pk2(ll[4],ll[5]), pk2(ll[6],ll[7]));
}

// conv_split4: the 4 weight matrices into g_w slots (y = slot)
__global__ __launch_bounds__(256) void conv_split4_kernel(
    const float* __restrict__ s0, const float* __restrict__ s1,
    const float* __restrict__ s2, const float* __restrict__ s3, int n8)
{
    int i = blockIdx.x * 256 + threadIdx.x;
    if (i >= n8) return;
    const float* srcs[4] = {s0, s1, s2, s3};
    const float* src = srcs[blockIdx.y];
    size_t slot = (size_t)blockIdx.y * D_ * D_;
    const float4* s = (const float4*)(src + (size_t)i * 8);
    float4 v0 = s[0], v1 = s[1];
    float f[8] = {v0.x, v0.y, v0.z, v0.w, v1.x, v1.y, v1.z, v1.w};
    float hh[8], ll[8];
#pragma unroll
    for (int e = 0; e < 8; e++) { hh[e] = bhi(f[e]); ll[e] = f[e] - hh[e]; }
    *(uint4*)(g_w_hi + slot + (size_t)i * 8) =
        make_uint4(pk2(hh[0],hh[1]), pk2(hh[2],hh[3]),
                   pk2(hh[4],hh[5]), pk2(hh[6],hh[7]));
    *(uint4*)(g_w_lo + slot + (size_t)i * 8) =
        make_uint4(pk2(ll[0],ll[1]), pk2(ll[2],ll[3]),
                   pk2(ll[4],ll[5]), pk2(ll[6],ll[7]));
}

// ---------------------------------------------------------------------------
// Generic bf16x3 mma GEMM: C[M,N] = A@B^T + bias[N].  Tile 128x128.
// __launch_bounds__(256,2): clamp regs to 128 -> 2 CTAs/SM (was 138 -> 1).
// ---------------------------------------------------------------------------
#define GM_STAGE 32768
#define GM_SMEM  (2*GM_STAGE)

__global__ __launch_bounds__(256, 2) void gemm_mma_nt(
    const __nv_bfloat16* __restrict__ Ah, const __nv_bfloat16* __restrict__ Al,
    const __nv_bfloat16* __restrict__ Bh, const __nv_bfloat16* __restrict__ Bl,
    const float* __restrict__ bias, float* __restrict__ C, int K, int N)
{
    extern __shared__ char smem[];
    const uint32_t sbase = smem_u32(smem);
    const int kc = K >> 5;

    const int tid  = threadIdx.x;
    const int wid  = tid >> 5, lane = tid & 31;
    const int wm   = wid >> 2, wn = wid & 3;

    const int i0 = blockIdx.y * 128;
    const int j0 = blockIdx.x * 128;

    const __nv_bfloat16* ah = Ah + (size_t)i0 * K;
    const __nv_bfloat16* al = Al + (size_t)i0 * K;
    const __nv_bfloat16* bh_ = Bh + (size_t)j0 * K;
    const __nv_bfloat16* bl_ = Bl + (size_t)j0 * K;

    auto issue = [&](int s, int c) {
        const uint32_t sb = sbase + s * GM_STAGE;
#pragma unroll
        for (int q = 0; q < 4; q++) {
            int u  = q * 256 + tid;
            int r  = u >> 3, cj = u & 7;
            const __nv_bfloat16* src =
                (cj < 4 ? ah : al) + (size_t)r * K + c * 32 + (cj & 3) * 8;
            CP_ASYNC16(sb + r * 128 + 16 * (cj ^ (r & 7)), src);
        }
#pragma unroll
        for (int q = 0; q < 4; q++) {
            int u  = q * 256 + tid;
            int r  = u >> 3, cj = u & 7;
            const __nv_bfloat16* src =
                (cj < 4 ? bh_ : bl_) + (size_t)r * K + c * 32 + (cj & 3) * 8;
            CP_ASYNC16(sb + 16384 + r * 128 + 16 * (cj ^ (r & 7)), src);
        }
    };

    float acc[4][4][4];
#pragma unroll
    for (int i = 0; i < 4; i++)
#pragma unroll
        for (int j = 0; j < 4; j++)
#pragma unroll
            for (int e = 0; e < 4; e++) acc[i][j][e] = 0.f;

    issue(0, 0);
    CP_COMMIT();

    const int lrow = (lane & 7) + 8 * ((lane >> 3) & 1);
    const int lchk = lane >> 4;

    for (int c = 0; c < kc; c++) {
        const int s = c & 1;
        if (c + 1 < kc) { issue(s ^ 1, c + 1); CP_COMMIT(); CP_WAIT(1); }
        else            { CP_WAIT(0); }
        __syncthreads();

        const uint32_t sA = sbase + s * GM_STAGE;
        const uint32_t sB = sA + 16384;

#pragma unroll
        for (int ks = 0; ks < 2; ks++) {
            uint32_t bh[4][2], bl[4][2];
#pragma unroll
            for (int g = 0; g < 2; g++) {
                int r  = wn * 32 + g * 16 + lrow;
                int ch = ks * 2 + lchk;
                uint32_t r0, r1, r2, r3;
                LDSM4(r0, r1, r2, r3, sB + r * 128 + 16 * ((ch)     ^ (r & 7)));
                bh[2*g][0] = r0; bh[2*g][1] = r2;
                bh[2*g+1][0] = r1; bh[2*g+1][1] = r3;
                LDSM4(r0, r1, r2, r3, sB + r * 128 + 16 * ((ch + 4) ^ (r & 7)));
                bl[2*g][0] = r0; bl[2*g][1] = r2;
                bl[2*g+1][0] = r1; bl[2*g+1][1] = r3;
            }
#pragma unroll
            for (int mf = 0; mf < 4; mf++) {
                int r  = wm * 64 + mf * 16 + lrow;
                int ch = ks * 2 + lchk;
                uint32_t ah_[4], al_[4];
                LDSM4(ah_[0], ah_[1], ah_[2], ah_[3],
                      sA + r * 128 + 16 * ((ch)     ^ (r & 7)));
                LDSM4(al_[0], al_[1], al_[2], al_[3],
                      sA + r * 128 + 16 * ((ch + 4) ^ (r & 7)));
#pragma unroll
                for (int nf = 0; nf < 4; nf++) {
                    MMA16816(acc[mf][nf], ah_, bh[nf]);
                    MMA16816(acc[mf][nf], ah_, bl[nf]);
                    MMA16816(acc[mf][nf], al_, bh[nf]);
                }
            }
        }
        __syncthreads();
    }

    const int rbase = i0 + wm * 64 + (lane >> 2);
    const int cbase = j0 + wn * 32 + 2 * (lane & 3);
#pragma unroll
    for (int mf = 0; mf < 4; mf++) {
        int gi = rbase + mf * 16;
        float* row0 = C + (size_t)gi * N;
        float* row1 = row0 + 8 * N;
#pragma unroll
        for (int nf = 0; nf < 4; nf++) {
            int gj = cbase + nf * 8;
            float b0 = bias[gj], b1 = bias[gj + 1];
            *(float2*)(row0 + gj) = make_float2(acc[mf][nf][0] + b0,
                                                acc[mf][nf][1] + b1);
            *(float2*)(row1 + gj) = make_float2(acc[mf][nf][2] + b0,
                                                acc[mf][nf][3] + b1);
        }
    }
}

// ---------------------------------------------------------------------------
// bcat[h, t*64+c] = bker[h,c,t]
// ---------------------------------------------------------------------------
__global__ void bcat_kernel(const float* __restrict__ bker)
{
    int n = blockIdx.x * blockDim.x + threadIdx.x;
    if (n >= H_ * NCAT) return;
    int h = n / NCAT, r = n % NCAT, t = r / DK_, c = r % DK_;
    g_bcat[n] = bker[(size_t)(h*DK_ + c) * KW_ + t];
}

// ---------------------------------------------------------------------------
// Qcat (fp32 SIMT, R6-proven): per (b,h):
//   Qcat[i, n=t*64+c] = sum_d q_s[i,d]*Wker[h,c,t,d] + bcat.  bf16 hi/lo out.
// grid (4, 8, 64)
// ---------------------------------------------------------------------------
__global__ __launch_bounds__(256) void qcat_kernel(const float* __restrict__ Wker)
{
    const int z = blockIdx.z;
    const int b = z >> 3, h = z & 7;
    const int bm = blockIdx.y * 128;
    const int bn = blockIdx.x * 128;
    const int tid = threadIdx.x;
    const int ty = tid >> 4, tx = tid & 15;

    __shared__ float As[16][128];
    __shared__ float Bs[16][128];

    const float* A = g_qs + (size_t)b * L_ * D_ + h * DK_;
    const float* W = Wker + (size_t)h * DK_ * NCAT;

    float acc[8][8];
#pragma unroll
    for (int i = 0; i < 8; i++)
#pragma unroll
        for (int j = 0; j < 8; j++) acc[i][j] = 0.f;

    const int lr = tid >> 2, lc = (tid & 3) << 2;

    for (int k0 = 0; k0 < DK_; k0 += 16) {
#pragma unroll
        for (int s = 0; s < 2; s++) {
            int row = lr + s * 64;
            float4 va = *(const float4*)(A + (size_t)(bm + row) * D_ + k0 + lc);
            As[lc+0][row] = va.x; As[lc+1][row] = va.y;
            As[lc+2][row] = va.z; As[lc+3][row] = va.w;
        }
        for (int idx = tid; idx < 512; idx += 256) {
            int nloc = idx >> 2;
            int kl   = (idx & 3) << 2;
            int gn = bn + nloc;
            float4 vb = make_float4(0,0,0,0);
            if (gn < NCAT) {
                int t = gn >> 6, c = gn & 63;
                vb = *(const float4*)(W + (size_t)c * NCAT + t * DK_ + k0 + kl);
            }
            Bs[kl+0][nloc] = vb.x; Bs[kl+1][nloc] = vb.y;
            Bs[kl+2][nloc] = vb.z; Bs[kl+3][nloc] = vb.w;
        }
        __syncthreads();
#pragma unroll
        for (int kk = 0; kk < 16; kk++) {
            float ra[8], rb[8];
            *(float4*)(ra)   = *(const float4*)&As[kk][ty*8];
            *(float4*)(ra+4) = *(const float4*)&As[kk][ty*8+4];
            *(float4*)(rb)   = *(const float4*)&Bs[kk][tx*4];
            *(float4*)(rb+4) = *(const float4*)&Bs[kk][64 + tx*4];
#pragma unroll
            for (int i = 0; i < 8; i++)
#pragma unroll
                for (int j = 0; j < 8; j++)
                    acc[i][j] = fmaf(ra[i], rb[j], acc[i][j]);
        }
        __syncthreads();
    }

    __nv_bfloat16* Ch = g_qcat_hi + (size_t)z * L_ * NCAT;
    __nv_bfloat16* Cl = g_qcat_lo + (size_t)z * L_ * NCAT;
    int c0g = bn + tx*4, c1g = bn + 64 + tx*4;
    float4 b0 = make_float4(0,0,0,0), b1 = make_float4(0,0,0,0);
    if (c0g < NCAT) b0 = *(const float4*)(g_bcat + h*NCAT + c0g);
    if (c1g < NCAT) b1 = *(const float4*)(g_bcat + h*NCAT + c1g);
#pragma unroll
    for (int i = 0; i < 8; i++) {
        size_t ro = (size_t)(bm + ty*8 + i) * NCAT;
        if (c0g < NCAT) {
            float v0 = acc[i][0]+b0.x, v1 = acc[i][1]+b0.y;
            float v2 = acc[i][2]+b0.z, v3 = acc[i][3]+b0.w;
            float h0 = bhi(v0), h1 = bhi(v1), h2 = bhi(v2), h3 = bhi(v3);
            *(uint2*)(Ch + ro + c0g) = make_uint2(pk2(h0,h1), pk2(h2,h3));
            *(uint2*)(Cl + ro + c0g) = make_uint2(pk2(v0-h0,v1-h1), pk2(v2-h2,v3-h3));
        }
        if (c1g < NCAT) {
            float v0 = acc[i][4]+b1.x, v1 = acc[i][5]+b1.y;
            float v2 = acc[i][6]+b1.z, v3 = acc[i][7]+b1.w;
            float h0 = bhi(v0), h1 = bhi(v1), h2 = bhi(v2), h3 = bhi(v3);
            *(uint2*)(Ch + ro + c1g) = make_uint2(pk2(h0,h1), pk2(h2,h3));
            *(uint2*)(Cl + ro + c1g) = make_uint2(pk2(v0-h0,v1-h1), pk2(v2-h2,v3-h3));
        }
    }
}

// ---------------------------------------------------------------------------
// Kcat prep: Kcat[z][j][t*64+c] = k_s[b][j+t-3][h*64+c] ; bf16 hi/lo
// ---------------------------------------------------------------------------
__global__ __launch_bounds__(256) void kcat_prep_kernel()
{
    int idx = blockIdx.x * 256 + threadIdx.x;
    if (idx >= B_*H_*L_*(NCAT/8)) return;
    int c8 = idx % (NCAT/8);
    int rest = idx / (NCAT/8);
    int j = rest & (L_-1);
    int z = rest >> 10;
    int b = z >> 3, h = z & 7;
    int cpos = c8 * 8;
    int t = cpos >> 6, cc = cpos & 63;
    int src = j + t - PAD_;
    float4 v0 = make_float4(0,0,0,0), v1 = make_float4(0,0,0,0);
    if (src >= 0 && src < L_) {
        const float* p = g_ks + ((size_t)(b*L_ + src)) * D_ + h*DK_ + cc;
        v0 = *(const float4*)p;
        v1 = *(const float4*)(p + 4);
    }
    float f[8] = {v0.x, v0.y, v0.z, v0.w, v1.x, v1.y, v1.z, v1.w};
    float hh[8], ll[8];
#pragma unroll
    for (int i = 0; i < 8; i++) { hh[i] = bhi(f[i]); ll[i] = f[i] - hh[i]; }
    size_t off = (size_t)z * L_ * NCAT + (size_t)j * NCAT + cpos;
    *(uint4*)(g_kcat_hi + off) = make_uint4(pk2(hh[0],hh[1]), pk2(hh[2],hh[3]),
                                            pk2(hh[4],hh[5]), pk2(hh[6],hh[7]));
    *(uint4*)(g_kcat_lo + off) = make_uint4(pk2(ll[0],ll[1]), pk2(ll[2],ll[3]),
                                            pk2(ll[4],ll[5]), pk2(ll[6],ll[7]));
}

// ---------------------------------------------------------------------------
// Logits (R6-proven): 128x128 tile, K=448 in 14 chunks, A=Qcat B=Kcat.
// No rowbias (row-constant terms cancel in softmax). grid (8, 8, 64).
// __launch_bounds__(256,2) for 2 CTAs/SM.
// ---------------------------------------------------------------------------
#define LOG_STAGE 32768
#define LOG_SMEM  (2*LOG_STAGE)

__global__ __launch_bounds__(256, 2) void logits_mma_kernel(float* __restrict__ attn)
{
    extern __shared__ char smem[];
    const uint32_t sbase = smem_u32(smem);

    const int tid  = threadIdx.x;
    const int wid  = tid >> 5, lane = tid & 31;
    const int wm   = wid >> 2, wn = wid & 3;

    const int z  = blockIdx.z;
    const int i0 = blockIdx.y * 128;
    const int j0 = blockIdx.x * 128;

    const __nv_bfloat16* qh = g_qcat_hi + (size_t)z * L_ * NCAT + (size_t)i0 * NCAT;
    const __nv_bfloat16* ql = g_qcat_lo + (size_t)z * L_ * NCAT + (size_t)i0 * NCAT;
    const __nv_bfloat16* kh = g_kcat_hi + (size_t)z * L_ * NCAT + (size_t)j0 * NCAT;
    const __nv_bfloat16* kl = g_kcat_lo + (size_t)z * L_ * NCAT + (size_t)j0 * NCAT;

    auto issue = [&](int s, int c) {
        const uint32_t sb = sbase + s * LOG_STAGE;
#pragma unroll
        for (int q = 0; q < 4; q++) {
            int u  = q * 256 + tid;
            int r  = u >> 3, cj = u & 7;
            const __nv_bfloat16* src =
                (cj < 4 ? qh : ql) + (size_t)r * NCAT + c * 32 + (cj & 3) * 8;
            CP_ASYNC16(sb + r * 128 + 16 * (cj ^ (r & 7)), src);
        }
#pragma unroll
        for (int q = 0; q < 4; q++) {
            int u  = q * 256 + tid;
            int r  = u >> 3, cj = u & 7;
            const __nv_bfloat16* src =
                (cj < 4 ? kh : kl) + (size_t)r * NCAT + c * 32 + (cj & 3) * 8;
            CP_ASYNC16(sb + 16384 + r * 128 + 16 * (cj ^ (r & 7)), src);
        }
    };

    float acc[4][4][4];
#pragma unroll
    for (int i = 0; i < 4; i++)
#pragma unroll
        for (int j = 0; j < 4; j++)
#pragma unroll
            for (int e = 0; e < 4; e++) acc[i][j][e] = 0.f;

    issue(0, 0);
    CP_COMMIT();

    const int lrow = (lane & 7) + 8 * ((lane >> 3) & 1);
    const int lchk = lane >> 4;

    for (int c = 0; c < 14; c++) {
        const int s = c & 1;
        if (c + 1 < 14) { issue(s ^ 1, c + 1); CP_COMMIT(); CP_WAIT(1); }
        else            { CP_WAIT(0); }
        __syncthreads();

        const uint32_t sA = sbase + s * LOG_STAGE;
        const uint32_t sB = sA + 16384;

#pragma unroll
        for (int ks = 0; ks < 2; ks++) {
            uint32_t bh[4][2], bl[4][2];
#pragma unroll
            for (int g = 0; g < 2; g++) {
                int r  = wn * 32 + g * 16 + lrow;
                int ch = ks * 2 + lchk;
                uint32_t r0, r1, r2, r3;
                LDSM4(r0, r1, r2, r3, sB + r * 128 + 16 * ((ch)     ^ (r & 7)));
                bh[2*g][0] = r0; bh[2*g][1] = r2;
                bh[2*g+1][0] = r1; bh[2*g+1][1] = r3;
                LDSM4(r0, r1, r2, r3, sB + r * 128 + 16 * ((ch + 4) ^ (r & 7)));
                bl[2*g][0] = r0; bl[2*g][1] = r2;
                bl[2*g+1][0] = r1; bl[2*g+1][1] = r3;
            }
#pragma unroll
            for (int mf = 0; mf < 4; mf++) {
                int r  = wm * 64 + mf * 16 + lrow;
                int ch = ks * 2 + lchk;
                uint32_t ah[4], al[4];
                LDSM4(ah[0], ah[1], ah[2], ah[3],
                      sA + r * 128 + 16 * ((ch)     ^ (r & 7)));
                LDSM4(al[0], al[1], al[2], al[3],
                      sA + r * 128 + 16 * ((ch + 4) ^ (r & 7)));
#pragma unroll
                for (int nf = 0; nf < 4; nf++) {
                    MMA16816(acc[mf][nf], ah, bh[nf]);
                    MMA16816(acc[mf][nf], ah, bl[nf]);
                    MMA16816(acc[mf][nf], al, bh[nf]);
                }
            }
        }
        __syncthreads();
    }

    const int rbase = i0 + wm * 64 + (lane >> 2);
    const int cbase = j0 + wn * 32 + 2 * (lane & 3);
#pragma unroll
    for (int mf = 0; mf < 4; mf++) {
        int gi0 = rbase + mf * 16;
        float* row0 = attn + ((size_t)z * L_ + gi0) * L_;
        float* row1 = row0 + 8 * L_;
#pragma unroll
        for (int nf = 0; nf < 4; nf++) {
            int gj = cbase + nf * 8;
            *(float2*)(row0 + gj) = make_float2(acc[mf][nf][0]*0.125f,
                                                acc[mf][nf][1]*0.125f);
            *(float2*)(row1 + gj) = make_float2(acc[mf][nf][2]*0.125f,
                                                acc[mf][nf][3]*0.125f);
        }
    }
}

// ---------------------------------------------------------------------------
// Row softmax in-place on attn; mask; head-0 duplicate.
// ---------------------------------------------------------------------------
__global__ __launch_bounds__(256) void softmax_kernel(
    float* __restrict__ attn, const unsigned char* __restrict__ mask,
    float* __restrict__ one_head)
{
    const int r = blockIdx.x;
    const int i = r & (L_-1);
    const int bh = r >> 10;
    const int h = bh & (H_-1), b = bh >> 3;
    float* row = attn + (size_t)r * L_;
    const unsigned char* mrow = mask + ((size_t)(b*L_ + i)) * L_;
    const int t4 = threadIdx.x * 4;

    float4 v = *(const float4*)(row + t4);
    uchar4 m = *(const uchar4*)(mrow + t4);
    float x0 = m.x ? -INFINITY : v.x;
    float x1 = m.y ? -INFINITY : v.y;
    float x2 = m.z ? -INFINITY : v.z;
    float x3 = m.w ? -INFINITY : v.w;

    __shared__ float sm[8], ss[8];
    float mx = fmaxf(fmaxf(x0, x1), fmaxf(x2, x3));
#pragma unroll
    for (int o = 16; o; o >>= 1) mx = fmaxf(mx, __shfl_xor_sync(0xffffffffu, mx, o));
    if ((threadIdx.x & 31) == 0) sm[threadIdx.x >> 5] = mx;
    __syncthreads();
    if (threadIdx.x < 32) {
        float t = (threadIdx.x < 8) ? sm[threadIdx.x] : -INFINITY;
#pragma unroll
        for (int o = 4; o; o >>= 1) t = fmaxf(t, __shfl_xor_sync(0xffffffffu, t, o));
        if (threadIdx.x == 0) sm[0] = t;
    }
    __syncthreads();
    mx = sm[0];

    float e0 = __expf(x0 - mx), e1 = __expf(x1 - mx);
    float e2 = __expf(x2 - mx), e3 = __expf(x3 - mx);
    float s = (e0 + e1) + (e2 + e3);
#pragma unroll
    for (int o = 16; o; o >>= 1) s += __shfl_xor_sync(0xffffffffu, s, o);
    if ((threadIdx.x & 31) == 0) ss[threadIdx.x >> 5] = s;
    __syncthreads();
    if (threadIdx.x < 32) {
        float t = (threadIdx.x < 8) ? ss[threadIdx.x] : 0.f;
#pragma unroll
        for (int o = 4; o; o >>= 1) t += __shfl_xor_sync(0xffffffffu, t, o);
        if (threadIdx.x == 0) ss[0] = t;
    }
    __syncthreads();
    float inv = 1.0f / ss[0];

    float4 o = make_float4(e0*inv, e1*inv, e2*inv, e3*inv);
    *(float4*)(row + t4) = o;
    if (h == 0)
        *(float4*)(one_head + ((size_t)(b*L_ + i)) * L_ + t4) = o;
}

// ---------------------------------------------------------------------------
// vt transpose: vt[z][n][k] = v_s[b][k][h*64+n], bf16 hi/lo.
// ---------------------------------------------------------------------------
__global__ __launch_bounds__(256) void vt_kernel()
{
    __shared__ float t[128][65];
    const int z = blockIdx.y;
    const int b = z >> 3, h = z & 7;
    const int k0 = blockIdx.x * 128;
    const int tid = threadIdx.x;

#pragma unroll
    for (int q = 0; q < 8; q++) {
        int u = q * 256 + tid;
        int r = u >> 4, c4 = (u & 15) * 4;
        float4 v = *(const float4*)(g_vs + ((size_t)(b*L_ + k0 + r)) * D_ + h*DK_ + c4);
        t[r][c4+0] = v.x; t[r][c4+1] = v.y; t[r][c4+2] = v.z; t[r][c4+3] = v.w;
    }
    __syncthreads();

#pragma unroll
    for (int q = 0; q < 4; q++) {
        int u = q * 256 + tid;
        int n = u >> 4, kk = (u & 15) * 8;
        float f[8], hh[8], ll[8];
#pragma unroll
        for (int e = 0; e < 8; e++) f[e] = t[kk + e][n];
#pragma unroll
        for (int e = 0; e < 8; e++) { hh[e] = bhi(f[e]); ll[e] = f[e] - hh[e]; }
        size_t off = (size_t)z * DK_ * L_ + (size_t)n * L_ + k0 + kk;
        *(uint4*)(g_vt_hi + off) = make_uint4(pk2(hh[0],hh[1]), pk2(hh[2],hh[3]),
                                              pk2(hh[4],hh[5]), pk2(hh[6],hh[7]));
        *(uint4*)(g_vt_lo + off) = make_uint4(pk2(ll[0],ll[1]), pk2(ll[2],ll[3]),
                                              pk2(ll[4],ll[5]), pk2(ll[6],ll[7]));
    }
}

// ---------------------------------------------------------------------------
// ctx via mma: per (b,h): C[1024,64] = attn @ v_head.
// ---------------------------------------------------------------------------
#define CTX_STAGE 24576

__global__ __launch_bounds__(256, 2) void ctx_mma_kernel(const float* __restrict__ attn)
{
    __shared__ char smem[2 * CTX_STAGE];
    const uint32_t sbase = smem_u32(smem);

    const int tid  = threadIdx.x;
    const int wid  = tid >> 5, lane = tid & 31;
    const int wm   = wid >> 2, wn = wid & 3;

    const int z  = blockIdx.y;
    const int b = z >> 3, h = z & 7;
    const int i0 = blockIdx.x * 128;

    const float* A = attn + ((size_t)z * L_ + i0) * L_;
    const __nv_bfloat16* vh = g_vt_hi + (size_t)z * DK_ * L_;
    const __nv_bfloat16* vl = g_vt_lo + (size_t)z * DK_ * L_;

    auto issueB = [&](int s, int c) {
        const uint32_t sb = sbase + s * CTX_STAGE + 16384;
#pragma unroll
        for (int q = 0; q < 2; q++) {
            int u  = q * 256 + tid;
            int r  = u >> 3, cj = u & 7;
            const __nv_bfloat16* src =
                (cj < 4 ? vh : vl) + (size_t)r * L_ + c * 32 + (cj & 3) * 8;
            CP_ASYNC16(sb + r * 128 + 16 * (cj ^ (r & 7)), src);
        }
    };
    float fa[2][8];
    auto ldgA = [&](int c) {
#pragma unroll
        for (int q = 0; q < 2; q++) {
            int u = q * 256 + tid;
            int r = u >> 2, seg = u & 3;
            const float4* p = (const float4*)(A + (size_t)r * L_ + c * 32 + seg * 8);
            float4 v0 = p[0], v1 = p[1];
            fa[q][0]=v0.x; fa[q][1]=v0.y; fa[q][2]=v0.z; fa[q][3]=v0.w;
            fa[q][4]=v1.x; fa[q][5]=v1.y; fa[q][6]=v1.z; fa[q][7]=v1.w;
        }
    };
    auto stsA = [&](int s) {
#pragma unroll
        for (int q = 0; q < 2; q++) {
            int u = q * 256 + tid;
            int r = u >> 2, seg = u & 3;
            float hh[8], ll[8];
#pragma unroll
            for (int e = 0; e < 8; e++) { hh[e] = bhi(fa[q][e]); ll[e] = fa[q][e] - hh[e]; }
            *(uint4*)(smem + s * CTX_STAGE + r * 128 + 16 * ((seg)     ^ (r & 7))) =
                make_uint4(pk2(hh[0],hh[1]), pk2(hh[2],hh[3]),
                           pk2(hh[4],hh[5]), pk2(hh[6],hh[7]));
            *(uint4*)(smem + s * CTX_STAGE + r * 128 + 16 * ((seg + 4) ^ (r & 7))) =
                make_uint4(pk2(ll[0],ll[1]), pk2(ll[2],ll[3]),
                           pk2(ll[4],ll[5]), pk2(ll[6],ll[7]));
        }
    };

    float acc[4][2][4];
#pragma unroll
    for (int i = 0; i < 4; i++)
#pragma unroll
        for (int j = 0; j < 2; j++)
#pragma unroll
            for (int e = 0; e < 4; e++) acc[i][j][e] = 0.f;

    ldgA(0);
    issueB(0, 0); CP_COMMIT();

    const int lrow = (lane & 7) + 8 * ((lane >> 3) & 1);
    const int lchk = lane >> 4;

    for (int c = 0; c < 32; c++) {
        const int s = c & 1;
        stsA(s);
        if (c + 1 < 32) {
            ldgA(c + 1);
            issueB(s ^ 1, c + 1); CP_COMMIT(); CP_WAIT(1);
        } else {
            CP_WAIT(0);
        }
        __syncthreads();

        const uint32_t sA = sbase + s * CTX_STAGE;
        const uint32_t sB = sA + 16384;

#pragma unroll
        for (int ks = 0; ks < 2; ks++) {
            uint32_t bh[2][2], bl[2][2];
            {
                int r  = wn * 16 + lrow;
                int ch = ks * 2 + lchk;
                uint32_t r0, r1, r2, r3;
                LDSM4(r0, r1, r2, r3, sB + r * 128 + 16 * ((ch)     ^ (r & 7)));
                bh[0][0] = r0; bh[0][1] = r2; bh[1][0] = r1; bh[1][1] = r3;
                LDSM4(r0, r1, r2, r3, sB + r * 128 + 16 * ((ch + 4) ^ (r & 7)));
                bl[0][0] = r0; bl[0][1] = r2; bl[1][0] = r1; bl[1][1] = r3;
            }
#pragma unroll
            for (int mf = 0; mf < 4; mf++) {
                int r  = wm * 64 + mf * 16 + lrow;
                int ch = ks * 2 + lchk;
                uint32_t ah[4], al[4];
                LDSM4(ah[0], ah[1], ah[2], ah[3],
                      sA + r * 128 + 16 * ((ch)     ^ (r & 7)));
                LDSM4(al[0], al[1], al[2], al[3],
                      sA + r * 128 + 16 * ((ch + 4) ^ (r & 7)));
#pragma unroll
                for (int nf = 0; nf < 2; nf++) {
                    MMA16816(acc[mf][nf], ah, bh[nf]);
                    MMA16816(acc[mf][nf], ah, bl[nf]);
                    MMA16816(acc[mf][nf], al, bh[nf]);
                }
            }
        }
        __syncthreads();
    }

    const int rbase = i0 + wm * 64 + (lane >> 2);
    const int cb = h * DK_ + wn * 16 + 2 * (lane & 3);
#pragma unroll
    for (int mf = 0; mf < 4; mf++) {
        int gi = rbase + mf * 16;
        size_t ro0 = ((size_t)(b * L_) + gi) * D_;
        size_t ro1 = ro0 + 8 * D_;
#pragma unroll
        for (int nf = 0; nf < 2; nf++) {
            int gj = cb + nf * 8;
            float v0 = acc[mf][nf][0], v1 = acc[mf][nf][1];
            float v2 = acc[mf][nf][2], v3 = acc[mf][nf][3];
            float h0 = bhi(v0), h1 = bhi(v1), h2 = bhi(v2), h3 = bhi(v3);
            *(unsigned*)(g_ctx_hi + ro0 + gj) = pk2(h0, h1);
            *(unsigned*)(g_ctx_lo + ro0 + gj) = pk2(v0 - h0, v1 - h1);
            *(unsigned*)(g_ctx_hi + ro1 + gj) = pk2(h2, h3);
            *(unsigned*)(g_ctx_lo + ro1 + gj) = pk2(v2 - h2, v3 - h3);
        }
    }
}

// ---------------------------------------------------------------------------
extern "C" void kernel_launch(void* const* d_in, const int* in_sizes, int n_in,
                              void* d_out, int out_size)
{
    const float* q      = (const float*)d_in[0];
    const float* k      = (const float*)d_in[1];
    const float* v      = (const float*)d_in[2];
    const unsigned char* mask = (const unsigned char*)d_in[3];
    const float* Wq     = (const float*)d_in[4];
    const float* bq     = (const float*)d_in[5];
    const float* Wk     = (const float*)d_in[6];
    const float* bk     = (const float*)d_in[7];
    const float* Wv     = (const float*)d_in[8];
    const float* bv     = (const float*)d_in[9];
    const float* Wker   = (const float*)d_in[10];
    const float* bker   = (const float*)d_in[11];
    const float* Wproj  = (const float*)d_in[15];
    const float* bproj  = (const float*)d_in[16];

    float* out      = (float*)d_out;
    float* attn     = out + (size_t)B_ * L_ * D_;
    float* one_head = attn + (size_t)B_ * H_ * L_ * L_;

    void* p;
    cudaGetSymbolAddress(&p, g_qs);  float* qs  = (float*)p;
    cudaGetSymbolAddress(&p, g_ks);  float* ks  = (float*)p;
    cudaGetSymbolAddress(&p, g_vs);  float* vs  = (float*)p;
    __nv_bfloat16 *iqh, *iql, *ikh, *ikl, *ivh, *ivl, *wh, *wl, *ch, *cl;
    cudaGetSymbolAddress(&p, g_inq_hi); iqh = (__nv_bfloat16*)p;
    cudaGetSymbolAddress(&p, g_inq_lo); iql = (__nv_bfloat16*)p;
    cudaGetSymbolAddress(&p, g_ink_hi); ikh = (__nv_bfloat16*)p;
    cudaGetSymbolAddress(&p, g_ink_lo); ikl = (__nv_bfloat16*)p;
    cudaGetSymbolAddress(&p, g_inv_hi); ivh = (__nv_bfloat16*)p;
    cudaGetSymbolAddress(&p, g_inv_lo); ivl = (__nv_bfloat16*)p;
    cudaGetSymbolAddress(&p, g_w_hi);   wh  = (__nv_bfloat16*)p;
    cudaGetSymbolAddress(&p, g_w_lo);   wl  = (__nv_bfloat16*)p;
    cudaGetSymbolAddress(&p, g_ctx_hi); ch  = (__nv_bfloat16*)p;
    cudaGetSymbolAddress(&p, g_ctx_lo); cl  = (__nv_bfloat16*)p;

    static bool attr_done = false;
    if (!attr_done) {
        cudaFuncSetAttribute(logits_mma_kernel,
            cudaFuncAttributeMaxDynamicSharedMemorySize, LOG_SMEM);
        cudaFuncSetAttribute(gemm_mma_nt,
            cudaFuncAttributeMaxDynamicSharedMemorySize, GM_SMEM);
        attr_done = true;
    }

    const int M = B_ * L_;        // 8192
    const int NE = M * D_;
    const int NW = D_ * D_;
    dim3 blk(256);

    // 0) splits + weight prep (fused launches)
    conv_split3_kernel<<<dim3((NE/8 + 255)/256, 3), 256>>>(q, k, v, NE/8);
    conv_split4_kernel<<<dim3((NW/8 + 255)/256, 4), 256>>>(Wq, Wk, Wv, Wproj, NW/8);
    bcat_kernel<<<(H_*NCAT + 255)/256, 256>>>(bker);

    // 1) projections (tensor cores)
    gemm_mma_nt<<<dim3(D_/128, M/128), blk, GM_SMEM>>>(iqh, iql, wh,        wl,        bq, qs, D_, D_);
    gemm_mma_nt<<<dim3(D_/128, M/128), blk, GM_SMEM>>>(ikh, ikl, wh + NW,   wl + NW,   bk, ks, D_, D_);
    gemm_mma_nt<<<dim3(D_/128, M/128), blk, GM_SMEM>>>(ivh, ivl, wh + 2*NW, wl + 2*NW, bv, vs, D_, D_);

    // 2) operand prep
    qcat_kernel<<<dim3(4, L_/128, B_*H_), blk>>>(Wker);
    kcat_prep_kernel<<<(B_*H_*L_*(NCAT/8) + 255)/256, 256>>>();
    vt_kernel<<<dim3(L_/128, B_*H_), blk>>>();

    // 3) tensor-core logits -> attn region (raw, scaled; no rowbias)
    logits_mma_kernel<<<dim3(L_/128, L_/128, B_*H_), 256, LOG_SMEM>>>(attn);

    // 4) softmax in place (+ one_head copy)
    softmax_kernel<<<B_*H_*L_, 256>>>(attn, mask, one_head);

    // 5) ctx = attn @ v_s -> g_ctx hi/lo
    ctx_mma_kernel<<<dim3(L_/128, B_*H_), blk>>>(attn);

    // 6) out = ctx @ Wproj^T + bproj
    gemm_mma_nt<<<dim3(D_/128, M/128), blk, GM_SMEM>>>(ch, cl, wh + 3*NW, wl + 3*NW, bproj, out, D_, D_);
}

// round 11
// speedup vs baseline: 1.1332x; 1.0343x over previous
#include <cuda_runtime.h>
#include <cuda_bf16.h>
#include <cstdint>

#define B_   8
#define L_   1024
#define D_   512
#define H_   8
#define DK_  64
#define KW_  7
#define PAD_ 3
#define NCAT 448    /* KW*DK */
#define WKN  512    /* padded Wker N for qcat GEMM */

// ---------------- scratch (device globals; no runtime allocation) ----------
__device__ float g_ks[B_*L_*D_];
__device__ float g_vs[B_*L_*D_];
__device__ float g_bcat[H_*WKN];
// q_s bf16 split (written directly by the q projection)
__device__ __align__(16) __nv_bfloat16 g_qs_hi[B_*L_*D_];
__device__ __align__(16) __nv_bfloat16 g_qs_lo[B_*L_*D_];
// Wker permuted+padded: [h][n=0..511][d=0..63]
__device__ __align__(16) __nv_bfloat16 g_wker_hi[H_*WKN*DK_];
__device__ __align__(16) __nv_bfloat16 g_wker_lo[H_*WKN*DK_];
// bf16 hi/lo operands for the logits GEMM (compact stride 448)
__device__ __align__(16) __nv_bfloat16 g_qcat_hi[(size_t)B_*H_*L_*NCAT];
__device__ __align__(16) __nv_bfloat16 g_qcat_lo[(size_t)B_*H_*L_*NCAT];
__device__ __align__(16) __nv_bfloat16 g_kcat_hi[(size_t)B_*H_*L_*NCAT];
__device__ __align__(16) __nv_bfloat16 g_kcat_lo[(size_t)B_*H_*L_*NCAT];
// projection inputs (bf16 split)
__device__ __align__(16) __nv_bfloat16 g_inq_hi[B_*L_*D_];
__device__ __align__(16) __nv_bfloat16 g_inq_lo[B_*L_*D_];
__device__ __align__(16) __nv_bfloat16 g_ink_hi[B_*L_*D_];
__device__ __align__(16) __nv_bfloat16 g_ink_lo[B_*L_*D_];
__device__ __align__(16) __nv_bfloat16 g_inv_hi[B_*L_*D_];
__device__ __align__(16) __nv_bfloat16 g_inv_lo[B_*L_*D_];
// weights (bf16 split): slots 0=Wq 1=Wk 2=Wv 3=Wproj
__device__ __align__(16) __nv_bfloat16 g_w_hi[4*D_*D_];
__device__ __align__(16) __nv_bfloat16 g_w_lo[4*D_*D_];
// v transposed per head: [z][n=0..63][k=0..1023]
__device__ __align__(16) __nv_bfloat16 g_vt_hi[(size_t)B_*H_*DK_*L_];
__device__ __align__(16) __nv_bfloat16 g_vt_lo[(size_t)B_*H_*DK_*L_];
// ctx in bf16 split, layout [B*L, 512]
__device__ __align__(16) __nv_bfloat16 g_ctx_hi[B_*L_*D_];
__device__ __align__(16) __nv_bfloat16 g_ctx_lo[B_*L_*D_];

// ====================== baseline-PTX tensor helpers ========================
static __device__ __forceinline__ uint32_t smem_u32(const void* p){
    uint32_t a;
    asm("{ .reg .u64 t; cvta.to.shared.u64 t, %1; cvt.u32.u64 %0, t; }"
        : "=r"(a) : "l"(p));
    return a;
}
#define CP_ASYNC16(dst, src) \
    asm volatile("cp.async.cg.shared.global [%0], [%1], 16;" \
                 :: "r"(dst), "l"(src) : "memory")
#define CP_COMMIT() asm volatile("cp.async.commit_group;" ::: "memory")
#define CP_WAIT(n)  asm volatile("cp.async.wait_group %0;" :: "n"(n) : "memory")
#define LDSM4(r0, r1, r2, r3, addr) \
    asm volatile("ldmatrix.sync.aligned.m8n8.x4.shared.b16 {%0,%1,%2,%3}, [%4];" \
                 : "=r"(r0), "=r"(r1), "=r"(r2), "=r"(r3) : "r"(addr))
#define MMA16816(d, a, b) \
    asm volatile("mma.sync.aligned.m16n8k16.row.col.f32.bf16.bf16.f32 " \
                 "{%0,%1,%2,%3},{%4,%5,%6,%7},{%8,%9},{%0,%1,%2,%3};" \
                 : "+f"((d)[0]), "+f"((d)[1]), "+f"((d)[2]), "+f"((d)[3]) \
                 : "r"((a)[0]), "r"((a)[1]), "r"((a)[2]), "r"((a)[3]), \
                   "r"((b)[0]), "r"((b)[1]))

static __device__ __forceinline__ unsigned pk2(float a, float b){
    __nv_bfloat162 t = __floats2bfloat162_rn(a, b);
    return *reinterpret_cast<unsigned*>(&t);
}
static __device__ __forceinline__ float bhi(float x){
    return __bfloat162float(__float2bfloat16_rn(x));
}

// ---------------------------------------------------------------------------
// conv_split3: fp32 -> bf16 hi/lo for q,k,v inputs in one launch (y = slot)
// ---------------------------------------------------------------------------
__global__ __launch_bounds__(256) void conv_split3_kernel(
    const float* __restrict__ s0, const float* __restrict__ s1,
    const float* __restrict__ s2, int n8)
{
    int i = blockIdx.x * 256 + threadIdx.x;
    if (i >= n8) return;
    const float* src; __nv_bfloat16 *dh, *dl;
    if (blockIdx.y == 0)      { src = s0; dh = g_inq_hi; dl = g_inq_lo; }
    else if (blockIdx.y == 1) { src = s1; dh = g_ink_hi; dl = g_ink_lo; }
    else                      { src = s2; dh = g_inv_hi; dl = g_inv_lo; }
    const float4* s = (const float4*)(src + (size_t)i * 8);
    float4 v0 = s[0], v1 = s[1];
    float f[8] = {v0.x, v0.y, v0.z, v0.w, v1.x, v1.y, v1.z, v1.w};
    float hh[8], ll[8];
#pragma unroll
    for (int e = 0; e < 8; e++) { hh[e] = bhi(f[e]); ll[e] = f[e] - hh[e]; }
    *(uint4*)(dh + (size_t)i * 8) = make_uint4(pk2(hh[0],hh[1]), pk2(hh[2],hh[3]),
                                               pk2(hh[4],hh[5]), pk2(hh[6],hh[7]));
    *(uint4*)(dl + (size_t)i * 8) = make_uint4(pk2(ll[0],ll[1]), pk2(ll[2],ll[3]),
                                               pk2(ll[4],ll[5]), pk2(ll[6],ll[7]));
}

// conv_split4: the 4 weight matrices into g_w slots (y = slot)
__global__ __launch_bounds__(256) void conv_split4_kernel(
    const float* __restrict__ s0, const float* __restrict__ s1,
    const float* __restrict__ s2, const float* __restrict__ s3, int n8)
{
    int i = blockIdx.x * 256 + threadIdx.x;
    if (i >= n8) return;
    const float* srcs[4] = {s0, s1, s2, s3};
    const float* src = srcs[blockIdx.y];
    size_t slot = (size_t)blockIdx.y * D_ * D_;
    const float4* s = (const float4*)(src + (size_t)i * 8);
    float4 v0 = s[0], v1 = s[1];
    float f[8] = {v0.x, v0.y, v0.z, v0.w, v1.x, v1.y, v1.z, v1.w};
    float hh[8], ll[8];
#pragma unroll
    for (int e = 0; e < 8; e++) { hh[e] = bhi(f[e]); ll[e] = f[e] - hh[e]; }
    *(uint4*)(g_w_hi + slot + (size_t)i * 8) =
        make_uint4(pk2(hh[0],hh[1]), pk2(hh[2],hh[3]),
                   pk2(hh[4],hh[5]), pk2(hh[6],hh[7]));
    *(uint4*)(g_w_lo + slot + (size_t)i * 8) =
        make_uint4(pk2(ll[0],ll[1]), pk2(ll[2],ll[3]),
                   pk2(ll[4],ll[5]), pk2(ll[6],ll[7]));
}

// ---------------------------------------------------------------------------
// wker_prep: g_wker[h][n][d] = Wker[h, n&63, n>>6, d] for n<448 else 0
// ---------------------------------------------------------------------------
__global__ __launch_bounds__(256) void wker_prep_kernel(const float* __restrict__ Wker)
{
    int idx = blockIdx.x * 256 + threadIdx.x;      // over 8*512*8
    if (idx >= H_ * WKN * 8) return;
    int d8 = (idx & 7) * 8;
    int n  = (idx >> 3) & (WKN - 1);
    int h  = idx >> 12;
    float f[8] = {0,0,0,0,0,0,0,0};
    if (n < NCAT) {
        int t = n >> 6, c = n & 63;
        const float* src = Wker + (((size_t)(h*DK_ + c)) * KW_ + t) * DK_ + d8;
        float4 v0 = *(const float4*)src, v1 = *(const float4*)(src + 4);
        f[0]=v0.x; f[1]=v0.y; f[2]=v0.z; f[3]=v0.w;
        f[4]=v1.x; f[5]=v1.y; f[6]=v1.z; f[7]=v1.w;
    }
    float hh[8], ll[8];
#pragma unroll
    for (int e = 0; e < 8; e++) { hh[e] = bhi(f[e]); ll[e] = f[e] - hh[e]; }
    size_t off = ((size_t)h * WKN + n) * DK_ + d8;
    *(uint4*)(g_wker_hi + off) = make_uint4(pk2(hh[0],hh[1]), pk2(hh[2],hh[3]),
                                            pk2(hh[4],hh[5]), pk2(hh[6],hh[7]));
    *(uint4*)(g_wker_lo + off) = make_uint4(pk2(ll[0],ll[1]), pk2(ll[2],ll[3]),
                                            pk2(ll[4],ll[5]), pk2(ll[6],ll[7]));
}

// ---------------------------------------------------------------------------
// bcat[h, n] = bker[h, n&63, n>>6] for n<448 else 0   (padded to 512)
// ---------------------------------------------------------------------------
__global__ void bcat_kernel(const float* __restrict__ bker)
{
    int n = blockIdx.x * blockDim.x + threadIdx.x;
    if (n >= H_ * WKN) return;
    int h = n >> 9, r = n & (WKN - 1), t = r >> 6, c = r & 63;
    g_bcat[n] = (r < NCAT) ? bker[(size_t)(h*DK_ + c) * KW_ + t] : 0.f;
}

// ---------------------------------------------------------------------------
// Generic bf16x3 mma GEMM: C[M,N] = A@B^T + bias[N].  Tile 128x128.
// Used for k/v/out projections.  2 CTAs/SM.
// ---------------------------------------------------------------------------
#define GM_STAGE 32768
#define GM_SMEM  (2*GM_STAGE)

__global__ __launch_bounds__(256, 2) void gemm_mma_nt(
    const __nv_bfloat16* __restrict__ Ah, const __nv_bfloat16* __restrict__ Al,
    const __nv_bfloat16* __restrict__ Bh, const __nv_bfloat16* __restrict__ Bl,
    const float* __restrict__ bias, float* __restrict__ C, int K, int N)
{
    extern __shared__ char smem[];
    const uint32_t sbase = smem_u32(smem);
    const int kc = K >> 5;

    const int tid  = threadIdx.x;
    const int wid  = tid >> 5, lane = tid & 31;
    const int wm   = wid >> 2, wn = wid & 3;

    const int i0 = blockIdx.y * 128;
    const int j0 = blockIdx.x * 128;

    const __nv_bfloat16* ah = Ah + (size_t)i0 * K;
    const __nv_bfloat16* al = Al + (size_t)i0 * K;
    const __nv_bfloat16* bh_ = Bh + (size_t)j0 * K;
    const __nv_bfloat16* bl_ = Bl + (size_t)j0 * K;

    auto issue = [&](int s, int c) {
        const uint32_t sb = sbase + s * GM_STAGE;
#pragma unroll
        for (int q = 0; q < 4; q++) {
            int u  = q * 256 + tid;
            int r  = u >> 3, cj = u & 7;
            const __nv_bfloat16* src =
                (cj < 4 ? ah : al) + (size_t)r * K + c * 32 + (cj & 3) * 8;
            CP_ASYNC16(sb + r * 128 + 16 * (cj ^ (r & 7)), src);
        }
#pragma unroll
        for (int q = 0; q < 4; q++) {
            int u  = q * 256 + tid;
            int r  = u >> 3, cj = u & 7;
            const __nv_bfloat16* src =
                (cj < 4 ? bh_ : bl_) + (size_t)r * K + c * 32 + (cj & 3) * 8;
            CP_ASYNC16(sb + 16384 + r * 128 + 16 * (cj ^ (r & 7)), src);
        }
    };

    float acc[4][4][4];
#pragma unroll
    for (int i = 0; i < 4; i++)
#pragma unroll
        for (int j = 0; j < 4; j++)
#pragma unroll
            for (int e = 0; e < 4; e++) acc[i][j][e] = 0.f;

    issue(0, 0);
    CP_COMMIT();

    const int lrow = (lane & 7) + 8 * ((lane >> 3) & 1);
    const int lchk = lane >> 4;

    for (int c = 0; c < kc; c++) {
        const int s = c & 1;
        if (c + 1 < kc) { issue(s ^ 1, c + 1); CP_COMMIT(); CP_WAIT(1); }
        else            { CP_WAIT(0); }
        __syncthreads();

        const uint32_t sA = sbase + s * GM_STAGE;
        const uint32_t sB = sA + 16384;

#pragma unroll
        for (int ks = 0; ks < 2; ks++) {
            uint32_t bh[4][2], bl[4][2];
#pragma unroll
            for (int g = 0; g < 2; g++) {
                int r  = wn * 32 + g * 16 + lrow;
                int ch = ks * 2 + lchk;
                uint32_t r0, r1, r2, r3;
                LDSM4(r0, r1, r2, r3, sB + r * 128 + 16 * ((ch)     ^ (r & 7)));
                bh[2*g][0] = r0; bh[2*g][1] = r2;
                bh[2*g+1][0] = r1; bh[2*g+1][1] = r3;
                LDSM4(r0, r1, r2, r3, sB + r * 128 + 16 * ((ch + 4) ^ (r & 7)));
                bl[2*g][0] = r0; bl[2*g][1] = r2;
                bl[2*g+1][0] = r1; bl[2*g+1][1] = r3;
            }
#pragma unroll
            for (int mf = 0; mf < 4; mf++) {
                int r  = wm * 64 + mf * 16 + lrow;
                int ch = ks * 2 + lchk;
                uint32_t ah_[4], al_[4];
                LDSM4(ah_[0], ah_[1], ah_[2], ah_[3],
                      sA + r * 128 + 16 * ((ch)     ^ (r & 7)));
                LDSM4(al_[0], al_[1], al_[2], al_[3],
                      sA + r * 128 + 16 * ((ch + 4) ^ (r & 7)));
#pragma unroll
                for (int nf = 0; nf < 4; nf++) {
                    MMA16816(acc[mf][nf], ah_, bh[nf]);
                    MMA16816(acc[mf][nf], ah_, bl[nf]);
                    MMA16816(acc[mf][nf], al_, bh[nf]);
                }
            }
        }
        __syncthreads();
    }

    const int rbase = i0 + wm * 64 + (lane >> 2);
    const int cbase = j0 + wn * 32 + 2 * (lane & 3);
#pragma unroll
    for (int mf = 0; mf < 4; mf++) {
        int gi = rbase + mf * 16;
        float* row0 = C + (size_t)gi * N;
        float* row1 = row0 + 8 * N;
#pragma unroll
        for (int nf = 0; nf < 4; nf++) {
            int gj = cbase + nf * 8;
            float b0 = bias[gj], b1 = bias[gj + 1];
            *(float2*)(row0 + gj) = make_float2(acc[mf][nf][0] + b0,
                                                acc[mf][nf][1] + b1);
            *(float2*)(row1 + gj) = make_float2(acc[mf][nf][2] + b0,
                                                acc[mf][nf][3] + b1);
        }
    }
}

// ---------------------------------------------------------------------------
// q-projection variant: identical mainloop, epilogue writes q_s as bf16 hi/lo
// ONLY (no fp32 output needed downstream).  K = N = 512 fixed.
// ---------------------------------------------------------------------------
__global__ __launch_bounds__(256, 2) void gemm_mma_qsplit(
    const __nv_bfloat16* __restrict__ Ah, const __nv_bfloat16* __restrict__ Al,
    const __nv_bfloat16* __restrict__ Bh, const __nv_bfloat16* __restrict__ Bl,
    const float* __restrict__ bias)
{
    extern __shared__ char smem[];
    const uint32_t sbase = smem_u32(smem);
    const int K = D_;

    const int tid  = threadIdx.x;
    const int wid  = tid >> 5, lane = tid & 31;
    const int wm   = wid >> 2, wn = wid & 3;

    const int i0 = blockIdx.y * 128;
    const int j0 = blockIdx.x * 128;

    const __nv_bfloat16* ah = Ah + (size_t)i0 * K;
    const __nv_bfloat16* al = Al + (size_t)i0 * K;
    const __nv_bfloat16* bh_ = Bh + (size_t)j0 * K;
    const __nv_bfloat16* bl_ = Bl + (size_t)j0 * K;

    auto issue = [&](int s, int c) {
        const uint32_t sb = sbase + s * GM_STAGE;
#pragma unroll
        for (int q = 0; q < 4; q++) {
            int u  = q * 256 + tid;
            int r  = u >> 3, cj = u & 7;
            const __nv_bfloat16* src =
                (cj < 4 ? ah : al) + (size_t)r * K + c * 32 + (cj & 3) * 8;
            CP_ASYNC16(sb + r * 128 + 16 * (cj ^ (r & 7)), src);
        }
#pragma unroll
        for (int q = 0; q < 4; q++) {
            int u  = q * 256 + tid;
            int r  = u >> 3, cj = u & 7;
            const __nv_bfloat16* src =
                (cj < 4 ? bh_ : bl_) + (size_t)r * K + c * 32 + (cj & 3) * 8;
            CP_ASYNC16(sb + 16384 + r * 128 + 16 * (cj ^ (r & 7)), src);
        }
    };

    float acc[4][4][4];
#pragma unroll
    for (int i = 0; i < 4; i++)
#pragma unroll
        for (int j = 0; j < 4; j++)
#pragma unroll
            for (int e = 0; e < 4; e++) acc[i][j][e] = 0.f;

    issue(0, 0);
    CP_COMMIT();

    const int lrow = (lane & 7) + 8 * ((lane >> 3) & 1);
    const int lchk = lane >> 4;

    for (int c = 0; c < 16; c++) {
        const int s = c & 1;
        if (c + 1 < 16) { issue(s ^ 1, c + 1); CP_COMMIT(); CP_WAIT(1); }
        else            { CP_WAIT(0); }
        __syncthreads();

        const uint32_t sA = sbase + s * GM_STAGE;
        const uint32_t sB = sA + 16384;

#pragma unroll
        for (int ks = 0; ks < 2; ks++) {
            uint32_t bh[4][2], bl[4][2];
#pragma unroll
            for (int g = 0; g < 2; g++) {
                int r  = wn * 32 + g * 16 + lrow;
                int ch = ks * 2 + lchk;
                uint32_t r0, r1, r2, r3;
                LDSM4(r0, r1, r2, r3, sB + r * 128 + 16 * ((ch)     ^ (r & 7)));
                bh[2*g][0] = r0; bh[2*g][1] = r2;
                bh[2*g+1][0] = r1; bh[2*g+1][1] = r3;
                LDSM4(r0, r1, r2, r3, sB + r * 128 + 16 * ((ch + 4) ^ (r & 7)));
                bl[2*g][0] = r0; bl[2*g][1] = r2;
                bl[2*g+1][0] = r1; bl[2*g+1][1] = r3;
            }
#pragma unroll
            for (int mf = 0; mf < 4; mf++) {
                int r  = wm * 64 + mf * 16 + lrow;
                int ch = ks * 2 + lchk;
                uint32_t ah_[4], al_[4];
                LDSM4(ah_[0], ah_[1], ah_[2], ah_[3],
                      sA + r * 128 + 16 * ((ch)     ^ (r & 7)));
                LDSM4(al_[0], al_[1], al_[2], al_[3],
                      sA + r * 128 + 16 * ((ch + 4) ^ (r & 7)));
#pragma unroll
                for (int nf = 0; nf < 4; nf++) {
                    MMA16816(acc[mf][nf], ah_, bh[nf]);
                    MMA16816(acc[mf][nf], ah_, bl[nf]);
                    MMA16816(acc[mf][nf], al_, bh[nf]);
                }
            }
        }
        __syncthreads();
    }

    const int rbase = i0 + wm * 64 + (lane >> 2);
    const int cbase = j0 + wn * 32 + 2 * (lane & 3);
#pragma unroll
    for (int mf = 0; mf < 4; mf++) {
        int gi = rbase + mf * 16;
        size_t ro0 = (size_t)gi * D_, ro1 = ro0 + 8 * D_;
#pragma unroll
        for (int nf = 0; nf < 4; nf++) {
            int gj = cbase + nf * 8;
            float b0 = bias[gj], b1 = bias[gj + 1];
            float v0 = acc[mf][nf][0] + b0, v1 = acc[mf][nf][1] + b1;
            float v2 = acc[mf][nf][2] + b0, v3 = acc[mf][nf][3] + b1;
            float h0 = bhi(v0), h1 = bhi(v1), h2 = bhi(v2), h3 = bhi(v3);
            *(unsigned*)(g_qs_hi + ro0 + gj) = pk2(h0, h1);
            *(unsigned*)(g_qs_lo + ro0 + gj) = pk2(v0 - h0, v1 - h1);
            *(unsigned*)(g_qs_hi + ro1 + gj) = pk2(h2, h3);
            *(unsigned*)(g_qs_lo + ro1 + gj) = pk2(v2 - h2, v3 - h3);
        }
    }
}

// ---------------------------------------------------------------------------
// qcat via mma: per z: Qcat[1024, n<448] = q_s_head[1024,64] @ wker[512,64]^T
//   + bcat. A = g_qs hi/lo (stride 512, head col slice). K=64 -> 2 chunks.
// grid (4 [n-tiles of 128], 8 [m-tiles], 64 z). Writes compact stride 448.
// ---------------------------------------------------------------------------
__global__ __launch_bounds__(256, 2) void qcat_mma_kernel()
{
    __shared__ char smem[2 * GM_STAGE];
    const uint32_t sbase = smem_u32(smem);

    const int tid  = threadIdx.x;
    const int wid  = tid >> 5, lane = tid & 31;
    const int wm   = wid >> 2, wn = wid & 3;

    const int z  = blockIdx.z;
    const int b = z >> 3, h = z & 7;
    const int i0 = blockIdx.y * 128;
    const int n0 = blockIdx.x * 128;

    const __nv_bfloat16* ah = g_qs_hi + ((size_t)(b*L_ + i0)) * D_ + h*DK_;
    const __nv_bfloat16* al = g_qs_lo + ((size_t)(b*L_ + i0)) * D_ + h*DK_;
    const __nv_bfloat16* bh_ = g_wker_hi + ((size_t)h * WKN + n0) * DK_;
    const __nv_bfloat16* bl_ = g_wker_lo + ((size_t)h * WKN + n0) * DK_;

    auto issue = [&](int s, int c) {
        const uint32_t sb = sbase + s * GM_STAGE;
#pragma unroll
        for (int q = 0; q < 4; q++) {
            int u  = q * 256 + tid;
            int r  = u >> 3, cj = u & 7;
            const __nv_bfloat16* src =
                (cj < 4 ? ah : al) + (size_t)r * D_ + c * 32 + (cj & 3) * 8;
            CP_ASYNC16(sb + r * 128 + 16 * (cj ^ (r & 7)), src);
        }
#pragma unroll
        for (int q = 0; q < 4; q++) {
            int u  = q * 256 + tid;
            int r  = u >> 3, cj = u & 7;
            const __nv_bfloat16* src =
                (cj < 4 ? bh_ : bl_) + (size_t)r * DK_ + c * 32 + (cj & 3) * 8;
            CP_ASYNC16(sb + 16384 + r * 128 + 16 * (cj ^ (r & 7)), src);
        }
    };

    float acc[4][4][4];
#pragma unroll
    for (int i = 0; i < 4; i++)
#pragma unroll
        for (int j = 0; j < 4; j++)
#pragma unroll
            for (int e = 0; e < 4; e++) acc[i][j][e] = 0.f;

    issue(0, 0);
    CP_COMMIT();

    const int lrow = (lane & 7) + 8 * ((lane >> 3) & 1);
    const int lchk = lane >> 4;

    for (int c = 0; c < 2; c++) {
        const int s = c & 1;
        if (c == 0) { issue(1, 1); CP_COMMIT(); CP_WAIT(1); }
        else        { CP_WAIT(0); }
        __syncthreads();

        const uint32_t sA = sbase + s * GM_STAGE;
        const uint32_t sB = sA + 16384;

#pragma unroll
        for (int ks = 0; ks < 2; ks++) {
            uint32_t bh[4][2], bl[4][2];
#pragma unroll
            for (int g = 0; g < 2; g++) {
                int r  = wn * 32 + g * 16 + lrow;
                int ch = ks * 2 + lchk;
                uint32_t r0, r1, r2, r3;
                LDSM4(r0, r1, r2, r3, sB + r * 128 + 16 * ((ch)     ^ (r & 7)));
                bh[2*g][0] = r0; bh[2*g][1] = r2;
                bh[2*g+1][0] = r1; bh[2*g+1][1] = r3;
                LDSM4(r0, r1, r2, r3, sB + r * 128 + 16 * ((ch + 4) ^ (r & 7)));
                bl[2*g][0] = r0; bl[2*g][1] = r2;
                bl[2*g+1][0] = r1; bl[2*g+1][1] = r3;
            }
#pragma unroll
            for (int mf = 0; mf < 4; mf++) {
                int r  = wm * 64 + mf * 16 + lrow;
                int ch = ks * 2 + lchk;
                uint32_t ah_[4], al_[4];
                LDSM4(ah_[0], ah_[1], ah_[2], ah_[3],
                      sA + r * 128 + 16 * ((ch)     ^ (r & 7)));
                LDSM4(al_[0], al_[1], al_[2], al_[3],
                      sA + r * 128 + 16 * ((ch + 4) ^ (r & 7)));
#pragma unroll
                for (int nf = 0; nf < 4; nf++) {
                    MMA16816(acc[mf][nf], ah_, bh[nf]);
                    MMA16816(acc[mf][nf], ah_, bl[nf]);
                    MMA16816(acc[mf][nf], al_, bh[nf]);
                }
            }
        }
        __syncthreads();
    }

    __nv_bfloat16* Ch = g_qcat_hi + (size_t)z * L_ * NCAT;
    __nv_bfloat16* Cl = g_qcat_lo + (size_t)z * L_ * NCAT;
    const int rbase = i0 + wm * 64 + (lane >> 2);
    const int cbase = n0 + wn * 32 + 2 * (lane & 3);
#pragma unroll
    for (int mf = 0; mf < 4; mf++) {
        int gi = rbase + mf * 16;
        size_t ro0 = (size_t)gi * NCAT, ro1 = ro0 + 8 * NCAT;
#pragma unroll
        for (int nf = 0; nf < 4; nf++) {
            int gj = cbase + nf * 8;
            if (gj >= NCAT) continue;
            float b0 = g_bcat[h*WKN + gj], b1 = g_bcat[h*WKN + gj + 1];
            float v0 = acc[mf][nf][0] + b0, v1 = acc[mf][nf][1] + b1;
            float v2 = acc[mf][nf][2] + b0, v3 = acc[mf][nf][3] + b1;
            float h0 = bhi(v0), h1 = bhi(v1), h2 = bhi(v2), h3 = bhi(v3);
            *(unsigned*)(Ch + ro0 + gj) = pk2(h0, h1);
            *(unsigned*)(Cl + ro0 + gj) = pk2(v0 - h0, v1 - h1);
            *(unsigned*)(Ch + ro1 + gj) = pk2(h2, h3);
            *(unsigned*)(Cl + ro1 + gj) = pk2(v2 - h2, v3 - h3);
        }
    }
}

// ---------------------------------------------------------------------------
// Kcat prep: Kcat[z][j][t*64+c] = k_s[b][j+t-3][h*64+c] ; bf16 hi/lo
// ---------------------------------------------------------------------------
__global__ __launch_bounds__(256) void kcat_prep_kernel()
{
    int idx = blockIdx.x * 256 + threadIdx.x;
    if (idx >= B_*H_*L_*(NCAT/8)) return;
    int c8 = idx % (NCAT/8);
    int rest = idx / (NCAT/8);
    int j = rest & (L_-1);
    int z = rest >> 10;
    int b = z >> 3, h = z & 7;
    int cpos = c8 * 8;
    int t = cpos >> 6, cc = cpos & 63;
    int src = j + t - PAD_;
    float4 v0 = make_float4(0,0,0,0), v1 = make_float4(0,0,0,0);
    if (src >= 0 && src < L_) {
        const float* p = g_ks + ((size_t)(b*L_ + src)) * D_ + h*DK_ + cc;
        v0 = *(const float4*)p;
        v1 = *(const float4*)(p + 4);
    }
    float f[8] = {v0.x, v0.y, v0.z, v0.w, v1.x, v1.y, v1.z, v1.w};
    float hh[8], ll[8];
#pragma unroll
    for (int i = 0; i < 8; i++) { hh[i] = bhi(f[i]); ll[i] = f[i] - hh[i]; }
    size_t off = (size_t)z * L_ * NCAT + (size_t)j * NCAT + cpos;
    *(uint4*)(g_kcat_hi + off) = make_uint4(pk2(hh[0],hh[1]), pk2(hh[2],hh[3]),
                                            pk2(hh[4],hh[5]), pk2(hh[6],hh[7]));
    *(uint4*)(g_kcat_lo + off) = make_uint4(pk2(ll[0],ll[1]), pk2(ll[2],ll[3]),
                                            pk2(ll[4],ll[5]), pk2(ll[6],ll[7]));
}

// ---------------------------------------------------------------------------
// Logits: 128x128 tile, K=448 in 14 chunks, A=Qcat B=Kcat, 3-stage pipeline.
// No rowbias (cancels in softmax).  grid (8, 8, 64).  2 CTAs/SM.
// ---------------------------------------------------------------------------
#define LOG_STAGE 32768
#define LOG_SMEM  (3*LOG_STAGE)

__global__ __launch_bounds__(256, 2) void logits_mma_kernel(float* __restrict__ attn)
{
    extern __shared__ char smem[];
    const uint32_t sbase = smem_u32(smem);

    const int tid  = threadIdx.x;
    const int wid  = tid >> 5, lane = tid & 31;
    const int wm   = wid >> 2, wn = wid & 3;

    const int z  = blockIdx.z;
    const int i0 = blockIdx.y * 128;
    const int j0 = blockIdx.x * 128;

    const __nv_bfloat16* qh = g_qcat_hi + (size_t)z * L_ * NCAT + (size_t)i0 * NCAT;
    const __nv_bfloat16* ql = g_qcat_lo + (size_t)z * L_ * NCAT + (size_t)i0 * NCAT;
    const __nv_bfloat16* kh = g_kcat_hi + (size_t)z * L_ * NCAT + (size_t)j0 * NCAT;
    const __nv_bfloat16* kl = g_kcat_lo + (size_t)z * L_ * NCAT + (size_t)j0 * NCAT;

    auto issue = [&](int s, int c) {
        const uint32_t sb = sbase + s * LOG_STAGE;
#pragma unroll
        for (int q = 0; q < 4; q++) {
            int u  = q * 256 + tid;
            int r  = u >> 3, cj = u & 7;
            const __nv_bfloat16* src =
                (cj < 4 ? qh : ql) + (size_t)r * NCAT + c * 32 + (cj & 3) * 8;
            CP_ASYNC16(sb + r * 128 + 16 * (cj ^ (r & 7)), src);
        }
#pragma unroll
        for (int q = 0; q < 4; q++) {
            int u  = q * 256 + tid;
            int r  = u >> 3, cj = u & 7;
            const __nv_bfloat16* src =
                (cj < 4 ? kh : kl) + (size_t)r * NCAT + c * 32 + (cj & 3) * 8;
            CP_ASYNC16(sb + 16384 + r * 128 + 16 * (cj ^ (r & 7)), src);
        }
    };

    float acc[4][4][4];
#pragma unroll
    for (int i = 0; i < 4; i++)
#pragma unroll
        for (int j = 0; j < 4; j++)
#pragma unroll
            for (int e = 0; e < 4; e++) acc[i][j][e] = 0.f;

    issue(0, 0); CP_COMMIT();
    issue(1, 1); CP_COMMIT();

    const int lrow = (lane & 7) + 8 * ((lane >> 3) & 1);
    const int lchk = lane >> 4;

    int stage = 0;
    for (int c = 0; c < 14; c++) {
        if (c + 2 < 14) {
            int s2 = stage + 2; if (s2 >= 3) s2 -= 3;
            issue(s2, c + 2); CP_COMMIT(); CP_WAIT(2);
        } else if (c + 1 < 14) {
            CP_WAIT(1);
        } else {
            CP_WAIT(0);
        }
        __syncthreads();

        const uint32_t sA = sbase + stage * LOG_STAGE;
        const uint32_t sB = sA + 16384;

#pragma unroll
        for (int ks = 0; ks < 2; ks++) {
            uint32_t bh[4][2], bl[4][2];
#pragma unroll
            for (int g = 0; g < 2; g++) {
                int r  = wn * 32 + g * 16 + lrow;
                int ch = ks * 2 + lchk;
                uint32_t r0, r1, r2, r3;
                LDSM4(r0, r1, r2, r3, sB + r * 128 + 16 * ((ch)     ^ (r & 7)));
                bh[2*g][0] = r0; bh[2*g][1] = r2;
                bh[2*g+1][0] = r1; bh[2*g+1][1] = r3;
                LDSM4(r0, r1, r2, r3, sB + r * 128 + 16 * ((ch + 4) ^ (r & 7)));
                bl[2*g][0] = r0; bl[2*g][1] = r2;
                bl[2*g+1][0] = r1; bl[2*g+1][1] = r3;
            }
#pragma unroll
            for (int mf = 0; mf < 4; mf++) {
                int r  = wm * 64 + mf * 16 + lrow;
                int ch = ks * 2 + lchk;
                uint32_t ah[4], al[4];
                LDSM4(ah[0], ah[1], ah[2], ah[3],
                      sA + r * 128 + 16 * ((ch)     ^ (r & 7)));
                LDSM4(al[0], al[1], al[2], al[3],
                      sA + r * 128 + 16 * ((ch + 4) ^ (r & 7)));
#pragma unroll
                for (int nf = 0; nf < 4; nf++) {
                    MMA16816(acc[mf][nf], ah, bh[nf]);
                    MMA16816(acc[mf][nf], ah, bl[nf]);
                    MMA16816(acc[mf][nf], al, bh[nf]);
                }
            }
        }
        __syncthreads();
        stage++; if (stage == 3) stage = 0;
    }

    const int rbase = i0 + wm * 64 + (lane >> 2);
    const int cbase = j0 + wn * 32 + 2 * (lane & 3);
#pragma unroll
    for (int mf = 0; mf < 4; mf++) {
        int gi0 = rbase + mf * 16;
        float* row0 = attn + ((size_t)z * L_ + gi0) * L_;
        float* row1 = row0 + 8 * L_;
#pragma unroll
        for (int nf = 0; nf < 4; nf++) {
            int gj = cbase + nf * 8;
            *(float2*)(row0 + gj) = make_float2(acc[mf][nf][0]*0.125f,
                                                acc[mf][nf][1]*0.125f);
            *(float2*)(row1 + gj) = make_float2(acc[mf][nf][2]*0.125f,
                                                acc[mf][nf][3]*0.125f);
        }
    }
}

// ---------------------------------------------------------------------------
// Row softmax in-place on attn; mask; head-0 duplicate.
// ---------------------------------------------------------------------------
__global__ __launch_bounds__(256) void softmax_kernel(
    float* __restrict__ attn, const unsigned char* __restrict__ mask,
    float* __restrict__ one_head)
{
    const int r = blockIdx.x;
    const int i = r & (L_-1);
    const int bh = r >> 10;
    const int h = bh & (H_-1), b = bh >> 3;
    float* row = attn + (size_t)r * L_;
    const unsigned char* mrow = mask + ((size_t)(b*L_ + i)) * L_;
    const int t4 = threadIdx.x * 4;

    float4 v = *(const float4*)(row + t4);
    uchar4 m = *(const uchar4*)(mrow + t4);
    float x0 = m.x ? -INFINITY : v.x;
    float x1 = m.y ? -INFINITY : v.y;
    float x2 = m.z ? -INFINITY : v.z;
    float x3 = m.w ? -INFINITY : v.w;

    __shared__ float sm[8], ss[8];
    float mx = fmaxf(fmaxf(x0, x1), fmaxf(x2, x3));
#pragma unroll
    for (int o = 16; o; o >>= 1) mx = fmaxf(mx, __shfl_xor_sync(0xffffffffu, mx, o));
    if ((threadIdx.x & 31) == 0) sm[threadIdx.x >> 5] = mx;
    __syncthreads();
    if (threadIdx.x < 32) {
        float t = (threadIdx.x < 8) ? sm[threadIdx.x] : -INFINITY;
#pragma unroll
        for (int o = 4; o; o >>= 1) t = fmaxf(t, __shfl_xor_sync(0xffffffffu, t, o));
        if (threadIdx.x == 0) sm[0] = t;
    }
    __syncthreads();
    mx = sm[0];

    float e0 = __expf(x0 - mx), e1 = __expf(x1 - mx);
    float e2 = __expf(x2 - mx), e3 = __expf(x3 - mx);
    float s = (e0 + e1) + (e2 + e3);
#pragma unroll
    for (int o = 16; o; o >>= 1) s += __shfl_xor_sync(0xffffffffu, s, o);
    if ((threadIdx.x & 31) == 0) ss[threadIdx.x >> 5] = s;
    __syncthreads();
    if (threadIdx.x < 32) {
        float t = (threadIdx.x < 8) ? ss[threadIdx.x] : 0.f;
#pragma unroll
        for (int o = 4; o; o >>= 1) t += __shfl_xor_sync(0xffffffffu, t, o);
        if (threadIdx.x == 0) ss[0] = t;
    }
    __syncthreads();
    float inv = 1.0f / ss[0];

    float4 o = make_float4(e0*inv, e1*inv, e2*inv, e3*inv);
    *(float4*)(row + t4) = o;
    if (h == 0)
        *(float4*)(one_head + ((size_t)(b*L_ + i)) * L_ + t4) = o;
}

// ---------------------------------------------------------------------------
// vt transpose: vt[z][n][k] = v_s[b][k][h*64+n], bf16 hi/lo.
// ---------------------------------------------------------------------------
__global__ __launch_bounds__(256) void vt_kernel()
{
    __shared__ float t[128][65];
    const int z = blockIdx.y;
    const int b = z >> 3, h = z & 7;
    const int k0 = blockIdx.x * 128;
    const int tid = threadIdx.x;

#pragma unroll
    for (int q = 0; q < 8; q++) {
        int u = q * 256 + tid;
        int r = u >> 4, c4 = (u & 15) * 4;
        float4 v = *(const float4*)(g_vs + ((size_t)(b*L_ + k0 + r)) * D_ + h*DK_ + c4);
        t[r][c4+0] = v.x; t[r][c4+1] = v.y; t[r][c4+2] = v.z; t[r][c4+3] = v.w;
    }
    __syncthreads();

#pragma unroll
    for (int q = 0; q < 4; q++) {
        int u = q * 256 + tid;
        int n = u >> 4, kk = (u & 15) * 8;
        float f[8], hh[8], ll[8];
#pragma unroll
        for (int e = 0; e < 8; e++) f[e] = t[kk + e][n];
#pragma unroll
        for (int e = 0; e < 8; e++) { hh[e] = bhi(f[e]); ll[e] = f[e] - hh[e]; }
        size_t off = (size_t)z * DK_ * L_ + (size_t)n * L_ + k0 + kk;
        *(uint4*)(g_vt_hi + off) = make_uint4(pk2(hh[0],hh[1]), pk2(hh[2],hh[3]),
                                              pk2(hh[4],hh[5]), pk2(hh[6],hh[7]));
        *(uint4*)(g_vt_lo + off) = make_uint4(pk2(ll[0],ll[1]), pk2(ll[2],ll[3]),
                                              pk2(ll[4],ll[5]), pk2(ll[6],ll[7]));
    }
}

// ---------------------------------------------------------------------------
// ctx via mma: per (b,h): C[1024,64] = attn @ v_head.
// ---------------------------------------------------------------------------
#define CTX_STAGE 24576

__global__ __launch_bounds__(256, 2) void ctx_mma_kernel(const float* __restrict__ attn)
{
    __shared__ char smem[2 * CTX_STAGE];
    const uint32_t sbase = smem_u32(smem);

    const int tid  = threadIdx.x;
    const int wid  = tid >> 5, lane = tid & 31;
    const int wm   = wid >> 2, wn = wid & 3;

    const int z  = blockIdx.y;
    const int b = z >> 3, h = z & 7;
    const int i0 = blockIdx.x * 128;

    const float* A = attn + ((size_t)z * L_ + i0) * L_;
    const __nv_bfloat16* vh = g_vt_hi + (size_t)z * DK_ * L_;
    const __nv_bfloat16* vl = g_vt_lo + (size_t)z * DK_ * L_;

    auto issueB = [&](int s, int c) {
        const uint32_t sb = sbase + s * CTX_STAGE + 16384;
#pragma unroll
        for (int q = 0; q < 2; q++) {
            int u  = q * 256 + tid;
            int r  = u >> 3, cj = u & 7;
            const __nv_bfloat16* src =
                (cj < 4 ? vh : vl) + (size_t)r * L_ + c * 32 + (cj & 3) * 8;
            CP_ASYNC16(sb + r * 128 + 16 * (cj ^ (r & 7)), src);
        }
    };
    float fa[2][8];
    auto ldgA = [&](int c) {
#pragma unroll
        for (int q = 0; q < 2; q++) {
            int u = q * 256 + tid;
            int r = u >> 2, seg = u & 3;
            const float4* p = (const float4*)(A + (size_t)r * L_ + c * 32 + seg * 8);
            float4 v0 = p[0], v1 = p[1];
            fa[q][0]=v0.x; fa[q][1]=v0.y; fa[q][2]=v0.z; fa[q][3]=v0.w;
            fa[q][4]=v1.x; fa[q][5]=v1.y; fa[q][6]=v1.z; fa[q][7]=v1.w;
        }
    };
    auto stsA = [&](int s) {
#pragma unroll
        for (int q = 0; q < 2; q++) {
            int u = q * 256 + tid;
            int r = u >> 2, seg = u & 3;
            float hh[8], ll[8];
#pragma unroll
            for (int e = 0; e < 8; e++) { hh[e] = bhi(fa[q][e]); ll[e] = fa[q][e] - hh[e]; }
            *(uint4*)(smem + s * CTX_STAGE + r * 128 + 16 * ((seg)     ^ (r & 7))) =
                make_uint4(pk2(hh[0],hh[1]), pk2(hh[2],hh[3]),
                           pk2(hh[4],hh[5]), pk2(hh[6],hh[7]));
            *(uint4*)(smem + s * CTX_STAGE + r * 128 + 16 * ((seg + 4) ^ (r & 7))) =
                make_uint4(pk2(ll[0],ll[1]), pk2(ll[2],ll[3]),
                           pk2(ll[4],ll[5]), pk2(ll[6],ll[7]));
        }
    };

    float acc[4][2][4];
#pragma unroll
    for (int i = 0; i < 4; i++)
#pragma unroll
        for (int j = 0; j < 2; j++)
#pragma unroll
            for (int e = 0; e < 4; e++) acc[i][j][e] = 0.f;

    ldgA(0);
    issueB(0, 0); CP_COMMIT();

    const int lrow = (lane & 7) + 8 * ((lane >> 3) & 1);
    const int lchk = lane >> 4;

    for (int c = 0; c < 32; c++) {
        const int s = c & 1;
        stsA(s);
        if (c + 1 < 32) {
            ldgA(c + 1);
            issueB(s ^ 1, c + 1); CP_COMMIT(); CP_WAIT(1);
        } else {
            CP_WAIT(0);
        }
        __syncthreads();

        const uint32_t sA = sbase + s * CTX_STAGE;
        const uint32_t sB = sA + 16384;

#pragma unroll
        for (int ks = 0; ks < 2; ks++) {
            uint32_t bh[2][2], bl[2][2];
            {
                int r  = wn * 16 + lrow;
                int ch = ks * 2 + lchk;
                uint32_t r0, r1, r2, r3;
                LDSM4(r0, r1, r2, r3, sB + r * 128 + 16 * ((ch)     ^ (r & 7)));
                bh[0][0] = r0; bh[0][1] = r2; bh[1][0] = r1; bh[1][1] = r3;
                LDSM4(r0, r1, r2, r3, sB + r * 128 + 16 * ((ch + 4) ^ (r & 7)));
                bl[0][0] = r0; bl[0][1] = r2; bl[1][0] = r1; bl[1][1] = r3;
            }
#pragma unroll
            for (int mf = 0; mf < 4; mf++) {
                int r  = wm * 64 + mf * 16 + lrow;
                int ch = ks * 2 + lchk;
                uint32_t ah[4], al[4];
                LDSM4(ah[0], ah[1], ah[2], ah[3],
                      sA + r * 128 + 16 * ((ch)     ^ (r & 7)));
                LDSM4(al[0], al[1], al[2], al[3],
                      sA + r * 128 + 16 * ((ch + 4) ^ (r & 7)));
#pragma unroll
                for (int nf = 0; nf < 2; nf++) {
                    MMA16816(acc[mf][nf], ah, bh[nf]);
                    MMA16816(acc[mf][nf], ah, bl[nf]);
                    MMA16816(acc[mf][nf], al, bh[nf]);
                }
            }
        }
        __syncthreads();
    }

    const int rbase = i0 + wm * 64 + (lane >> 2);
    const int cb = h * DK_ + wn * 16 + 2 * (lane & 3);
#pragma unroll
    for (int mf = 0; mf < 4; mf++) {
        int gi = rbase + mf * 16;
        size_t ro0 = ((size_t)(b * L_) + gi) * D_;
        size_t ro1 = ro0 + 8 * D_;
#pragma unroll
        for (int nf = 0; nf < 2; nf++) {
            int gj = cb + nf * 8;
            float v0 = acc[mf][nf][0], v1 = acc[mf][nf][1];
            float v2 = acc[mf][nf][2], v3 = acc[mf][nf][3];
            float h0 = bhi(v0), h1 = bhi(v1), h2 = bhi(v2), h3 = bhi(v3);
            *(unsigned*)(g_ctx_hi + ro0 + gj) = pk2(h0, h1);
            *(unsigned*)(g_ctx_lo + ro0 + gj) = pk2(v0 - h0, v1 - h1);
            *(unsigned*)(g_ctx_hi + ro1 + gj) = pk2(h2, h3);
            *(unsigned*)(g_ctx_lo + ro1 + gj) = pk2(v2 - h2, v3 - h3);
        }
    }
}

// ---------------------------------------------------------------------------
extern "C" void kernel_launch(void* const* d_in, const int* in_sizes, int n_in,
                              void* d_out, int out_size)
{
    const float* q      = (const float*)d_in[0];
    const float* k      = (const float*)d_in[1];
    const float* v      = (const float*)d_in[2];
    const unsigned char* mask = (const unsigned char*)d_in[3];
    const float* Wq     = (const float*)d_in[4];
    const float* bq     = (const float*)d_in[5];
    const float* Wk     = (const float*)d_in[6];
    const float* bk     = (const float*)d_in[7];
    const float* Wv     = (const float*)d_in[8];
    const float* bv     = (const float*)d_in[9];
    const float* Wker   = (const float*)d_in[10];
    const float* bker   = (const float*)d_in[11];
    const float* Wproj  = (const float*)d_in[15];
    const float* bproj  = (const float*)d_in[16];

    float* out      = (float*)d_out;
    float* attn     = out + (size_t)B_ * L_ * D_;
    float* one_head = attn + (size_t)B_ * H_ * L_ * L_;

    void* p;
    cudaGetSymbolAddress(&p, g_ks);  float* ks  = (float*)p;
    cudaGetSymbolAddress(&p, g_vs);  float* vs  = (float*)p;
    __nv_bfloat16 *iqh, *iql, *ikh, *ikl, *ivh, *ivl, *wh, *wl, *ch, *cl;
    cudaGetSymbolAddress(&p, g_inq_hi); iqh = (__nv_bfloat16*)p;
    cudaGetSymbolAddress(&p, g_inq_lo); iql = (__nv_bfloat16*)p;
    cudaGetSymbolAddress(&p, g_ink_hi); ikh = (__nv_bfloat16*)p;
    cudaGetSymbolAddress(&p, g_ink_lo); ikl = (__nv_bfloat16*)p;
    cudaGetSymbolAddress(&p, g_inv_hi); ivh = (__nv_bfloat16*)p;
    cudaGetSymbolAddress(&p, g_inv_lo); ivl = (__nv_bfloat16*)p;
    cudaGetSymbolAddress(&p, g_w_hi);   wh  = (__nv_bfloat16*)p;
    cudaGetSymbolAddress(&p, g_w_lo);   wl  = (__nv_bfloat16*)p;
    cudaGetSymbolAddress(&p, g_ctx_hi); ch  = (__nv_bfloat16*)p;
    cudaGetSymbolAddress(&p, g_ctx_lo); cl  = (__nv_bfloat16*)p;

    static bool attr_done = false;
    if (!attr_done) {
        cudaFuncSetAttribute(logits_mma_kernel,
            cudaFuncAttributeMaxDynamicSharedMemorySize, LOG_SMEM);
        cudaFuncSetAttribute(gemm_mma_nt,
            cudaFuncAttributeMaxDynamicSharedMemorySize, GM_SMEM);
        cudaFuncSetAttribute(gemm_mma_qsplit,
            cudaFuncAttributeMaxDynamicSharedMemorySize, GM_SMEM);
        attr_done = true;
    }

    const int M = B_ * L_;        // 8192
    const int NE = M * D_;
    const int NW = D_ * D_;
    dim3 blk(256);

    // 0) splits + weight prep (fused launches)
    conv_split3_kernel<<<dim3((NE/8 + 255)/256, 3), 256>>>(q, k, v, NE/8);
    conv_split4_kernel<<<dim3((NW/8 + 255)/256, 4), 256>>>(Wq, Wk, Wv, Wproj, NW/8);
    wker_prep_kernel<<<(H_*WKN*8 + 255)/256, 256>>>(Wker);
    bcat_kernel<<<(H_*WKN + 255)/256, 256>>>(bker);

    // 1) projections (tensor cores); q writes bf16 split directly
    gemm_mma_qsplit<<<dim3(D_/128, M/128), blk, GM_SMEM>>>(iqh, iql, wh, wl, bq);
    gemm_mma_nt<<<dim3(D_/128, M/128), blk, GM_SMEM>>>(ikh, ikl, wh + NW,   wl + NW,   bk, ks, D_, D_);
    gemm_mma_nt<<<dim3(D_/128, M/128), blk, GM_SMEM>>>(ivh, ivl, wh + 2*NW, wl + 2*NW, bv, vs, D_, D_);

    // 2) operand prep (qcat on tensor cores now)
    qcat_mma_kernel<<<dim3(WKN/128, L_/128, B_*H_), blk>>>();
    kcat_prep_kernel<<<(B_*H_*L_*(NCAT/8) + 255)/256, 256>>>();
    vt_kernel<<<dim3(L_/128, B_*H_), blk>>>();

    // 3) tensor-core logits -> attn region (raw, scaled; no rowbias)
    logits_mma_kernel<<<dim3(L_/128, L_/128, B_*H_), 256, LOG_SMEM>>>(attn);

    // 4) softmax in place (+ one_head copy)
    softmax_kernel<<<B_*H_*L_, 256>>>(attn, mask, one_head);

    // 5) ctx = attn @ v_s -> g_ctx hi/lo
    ctx_mma_kernel<<<dim3(L_/128, B_*H_), blk>>>(attn);

    // 6) out = ctx @ Wproj^T + bproj
    gemm_mma_nt<<<dim3(D_/128, M/128), blk, GM_SMEM>>>(ch, cl, wh + 3*NW, wl + 3*NW, bproj, out, D_, D_);
}